// round 12
// baseline (speedup 1.0000x reference)
#include <cuda_runtime.h>
#include <cuda_fp16.h>
#include <math.h>
#include <stdint.h>

#define Bv 2
#define Nv 2048
#define Dv 1024
#define Hv 16
#define Dhv 64
#define Mrows (Bv * Nv)   // 4096

// ---------------------------------------------------------------------------
// Scratch (fp16 split formats)
// ---------------------------------------------------------------------------
__device__ __half g_x16[Mrows * Dv];
__device__ __half g_Wqh16[Dv * Dv], g_Wql16[Dv * Dv];
__device__ __half g_Wkh16[Dv * Dv], g_Wkl16[Dv * Dv];
__device__ __half g_Wvh16[Dv * Dv], g_Wvl16[Dv * Dv];
__device__ __half g_Woh16[Dv * Dv], g_Wol16[Dv * Dv];
__device__ __half g_Qh[Mrows * Dv], g_Kh[Mrows * Dv];
__device__ __half g_Vh[Mrows * Dv];
__device__ __half g_Of[Mrows * Dv];
__device__ float  g_qn[Bv * Hv * Nv], g_kn[Bv * Hv * Nv];

// ---------------------------------------------------------------------------
// Helpers (plain-sm_100-safe PTX only)
// ---------------------------------------------------------------------------
__device__ __forceinline__ uint32_t smem_u32(const void* p) {
    uint32_t a;
    asm("{ .reg .u64 t; cvta.to.shared.u64 t, %1; cvt.u32.u64 %0, t; }" : "=r"(a) : "l"(p));
    return a;
}
__device__ __forceinline__ void cp16(uint32_t dst, const void* src) {
    asm volatile("cp.async.cg.shared.global [%0], [%1], 16;" :: "r"(dst), "l"(src) : "memory");
}
#define CP_COMMIT() asm volatile("cp.async.commit_group;" ::: "memory")
#define CP_WAIT(n)  asm volatile("cp.async.wait_group %0;" :: "n"(n) : "memory")

#define LDSM4(r0, r1, r2, r3, addr) \
    asm volatile("ldmatrix.sync.aligned.m8n8.x4.shared.b16 {%0,%1,%2,%3}, [%4];" \
        : "=r"(r0), "=r"(r1), "=r"(r2), "=r"(r3) : "r"(addr))
#define LDSM4T(r0, r1, r2, r3, addr) \
    asm volatile("ldmatrix.sync.aligned.m8n8.x4.trans.shared.b16 {%0,%1,%2,%3}, [%4];" \
        : "=r"(r0), "=r"(r1), "=r"(r2), "=r"(r3) : "r"(addr))

__device__ __forceinline__ void mma_f16(float* d, const uint32_t* a, uint32_t b0, uint32_t b1) {
    asm volatile("mma.sync.aligned.m16n8k16.row.col.f32.f16.f16.f32 "
        "{%0,%1,%2,%3}, {%4,%5,%6,%7}, {%8,%9}, {%0,%1,%2,%3};"
        : "+f"(d[0]), "+f"(d[1]), "+f"(d[2]), "+f"(d[3])
        : "r"(a[0]), "r"(a[1]), "r"(a[2]), "r"(a[3]), "r"(b0), "r"(b1));
}

__device__ __forceinline__ uint32_t pack_h2(float lo, float hi) {
    __half2 h = __floats2half2_rn(lo, hi);
    return *(uint32_t*)&h;
}
__device__ __forceinline__ void hsplit2(float a, float b, uint32_t& h, uint32_t& l) {
    h = pack_h2(a, b);
    float2 f = __half22float2(*(__half2*)&h);
    l = pack_h2(a - f.x, b - f.y);
}

__device__ __forceinline__ float f_lg2(float x) { float r; asm("lg2.approx.f32 %0, %1;" : "=f"(r) : "f"(x)); return r; }
__device__ __forceinline__ float f_ex2(float x) { float r; asm("ex2.approx.f32 %0, %1;" : "=f"(r) : "f"(x)); return r; }
__device__ __forceinline__ float f_sqrt(float x){ float r; asm("sqrt.approx.f32 %0, %1;" : "=f"(r) : "f"(x)); return r; }

// ---------------------------------------------------------------------------
// Prep: x -> fp16; each W -> fp16 hi/lo
// ---------------------------------------------------------------------------
__global__ void prep_split(const float* __restrict__ x, const float* __restrict__ Wq,
                           const float* __restrict__ Wk, const float* __restrict__ Wv,
                           const float* __restrict__ Wo) {
    int i = (blockIdx.x * 256 + threadIdx.x) * 4;
    if (blockIdx.z == 0) {
        if (i >= Mrows * Dv) return;
        float4 v = *(const float4*)(x + i);
        uint32_t h01 = pack_h2(v.x, v.y), h23 = pack_h2(v.z, v.w);
        *(uint32_t*)(g_x16 + i) = h01; *(uint32_t*)(g_x16 + i + 2) = h23;
        return;
    }
    const float* src; __half *hi, *lo;
    switch (blockIdx.z) {
        case 1:  src = Wq; hi = g_Wqh16; lo = g_Wql16; break;
        case 2:  src = Wk; hi = g_Wkh16; lo = g_Wkl16; break;
        case 3:  src = Wv; hi = g_Wvh16; lo = g_Wvl16; break;
        default: src = Wo; hi = g_Woh16; lo = g_Wol16; break;
    }
    if (i >= Dv * Dv) return;
    float4 v = *(const float4*)(src + i);
    uint32_t h01, l01, h23, l23;
    hsplit2(v.x, v.y, h01, l01);
    hsplit2(v.z, v.w, h23, l23);
    *(uint32_t*)(hi + i) = h01; *(uint32_t*)(hi + i + 2) = h23;
    *(uint32_t*)(lo + i) = l01; *(uint32_t*)(lo + i + 2) = l23;
}

// ---------------------------------------------------------------------------
// 2xFP16 GEMM (R11-proven, unchanged): D = Ah @ (Wh + Wl)^T.
// ---------------------------------------------------------------------------
#define GSTAGE    24576
#define GEMM_SMEM (3 * GSTAGE)

__device__ __forceinline__ void gemm_cp_body(
    const __half* __restrict__ Ah,
    const __half* __restrict__ Wh, const __half* __restrict__ Wl,
    int mode, __half* outH, float* fout, float* nrm_out)
{
    extern __shared__ char smem[];
    const uint32_t SB = smem_u32(smem);
    const int t = threadIdx.x, L = t & 31, wid = t >> 5;
    const int wm = wid >> 2, wn = wid & 3;
    const int m0 = blockIdx.y * 128, n0 = blockIdx.x * 128;

    auto issue = [&](int kc) {
        const int k0 = kc * 32;
        const uint32_t sbase = SB + (uint32_t)(kc % 3) * GSTAGE;
#pragma unroll
        for (int u = 0; u < 6; u++) {
            int idx = t + 256 * u;
            int tile = idx >> 9, r = (idx >> 2) & 127, ch = idx & 3;
            const __half* base = (tile == 0) ? Ah : (tile == 1) ? Wh : Wl;
            int grow = ((tile == 0) ? m0 : n0) + r;
            const void* src = base + (size_t)grow * 1024 + k0 + ch * 8;
            cp16(sbase + tile * 8192 + r * 64 + (((ch ^ ((r >> 1) & 3)) << 4)), src);
        }
        CP_COMMIT();
    };

    issue(0);
    issue(1);

    const int arow = wm * 64 + (L & 15);
    const int brow = wn * 32 + ((L >> 4) & 1) * 8 + (L & 7);
    const uint32_t aRowOff = (uint32_t)(arow * 64);
    const uint32_t bhOff = (uint32_t)(8192 + brow * 64);
    const uint32_t blOff = (uint32_t)(16384 + brow * 64);
    const uint32_t aXr = (uint32_t)((arow >> 1) & 3);
    const uint32_t bXr = (uint32_t)((brow >> 1) & 3);

    float acc[4][4][4];
#pragma unroll
    for (int i = 0; i < 4; i++)
#pragma unroll
        for (int j = 0; j < 4; j++)
#pragma unroll
            for (int r = 0; r < 4; r++) acc[i][j][r] = 0.0f;

#pragma unroll 1
    for (int kc = 0; kc < 32; kc++) {
        if (kc < 31) { CP_WAIT(1); } else { CP_WAIT(0); }
        __syncthreads();
        if (kc + 2 < 32) issue(kc + 2);
        const uint32_t sb = SB + (uint32_t)(kc % 3) * GSTAGE;
#pragma unroll
        for (int js = 0; js < 2; js++) {
            const uint32_t achunk = (uint32_t)((((2 * js + (L >> 4)) ^ aXr) << 4));
            const uint32_t bchunk = (uint32_t)((((2 * js + ((L >> 3) & 1)) ^ bXr) << 4));
            uint32_t ah[4][4];
#pragma unroll
            for (int i = 0; i < 4; i++)
                LDSM4(ah[i][0], ah[i][1], ah[i][2], ah[i][3], sb + aRowOff + i * 1024 + achunk);
#pragma unroll
            for (int jp = 0; jp < 2; jp++) {
                uint32_t bh[4], bl[4];
                LDSM4(bh[0], bh[1], bh[2], bh[3], sb + bhOff + jp * 1024 + bchunk);
                LDSM4(bl[0], bl[1], bl[2], bl[3], sb + blOff + jp * 1024 + bchunk);
#pragma unroll
                for (int i = 0; i < 4; i++) {
                    mma_f16(acc[i][jp * 2],     ah[i], bh[0], bh[1]);
                    mma_f16(acc[i][jp * 2 + 1], ah[i], bh[2], bh[3]);
                }
#pragma unroll
                for (int i = 0; i < 4; i++) {
                    mma_f16(acc[i][jp * 2],     ah[i], bl[0], bl[1]);
                    mma_f16(acc[i][jp * 2 + 1], ah[i], bl[2], bl[3]);
                }
            }
        }
    }

    const int rb = m0 + wm * 64 + (L >> 2);
    const int cb = n0 + wn * 32 + (L & 3) * 2;

    if (mode <= 1) {
        float p0s[4], p1s[4];
#pragma unroll
        for (int i = 0; i < 4; i++) {
            float s0 = 0.0f, s1 = 0.0f;
#pragma unroll
            for (int j = 0; j < 4; j++) {
                const int r = rb + i * 16, c = cb + j * 8;
                *(__half2*)(outH + (size_t)r * 1024 + c)       = __floats2half2_rn(acc[i][j][0], acc[i][j][1]);
                *(__half2*)(outH + (size_t)(r + 8) * 1024 + c) = __floats2half2_rn(acc[i][j][2], acc[i][j][3]);
                s0 = fmaf(acc[i][j][0], acc[i][j][0], fmaf(acc[i][j][1], acc[i][j][1], s0));
                s1 = fmaf(acc[i][j][2], acc[i][j][2], fmaf(acc[i][j][3], acc[i][j][3], s1));
            }
            s0 += __shfl_xor_sync(0xffffffffu, s0, 1);
            s0 += __shfl_xor_sync(0xffffffffu, s0, 2);
            s1 += __shfl_xor_sync(0xffffffffu, s1, 1);
            s1 += __shfl_xor_sync(0xffffffffu, s1, 2);
            p0s[i] = s0; p1s[i] = s1;
        }
        __syncthreads();
        float* part = (float*)smem;
        if ((L & 3) == 0) {
#pragma unroll
            for (int i = 0; i < 4; i++) {
                int r0 = wm * 64 + (L >> 2) + i * 16;
                part[r0 * 4 + wn] = p0s[i];
                part[(r0 + 8) * 4 + wn] = p1s[i];
            }
        }
        __syncthreads();
        {
            int row = t >> 1, ph = t & 1;
            float s = part[row * 4 + 2 * ph] + part[row * 4 + 2 * ph + 1];
            int grow = m0 + row, head = (n0 >> 6) + ph;
            int b = grow >> 11, n = grow & 2047;
            nrm_out[((b << 4) + head) * Nv + n] = s;
        }
    } else if (mode == 2) {
#pragma unroll
        for (int i = 0; i < 4; i++)
#pragma unroll
            for (int j = 0; j < 4; j++) {
                const int r = rb + i * 16, c = cb + j * 8;
                *(__half2*)(outH + (size_t)r * 1024 + c)       = __floats2half2_rn(acc[i][j][0], acc[i][j][1]);
                *(__half2*)(outH + (size_t)(r + 8) * 1024 + c) = __floats2half2_rn(acc[i][j][2], acc[i][j][3]);
            }
    } else {
#pragma unroll
        for (int i = 0; i < 4; i++)
#pragma unroll
            for (int j = 0; j < 4; j++) {
                const int r = rb + i * 16, cx = cb + j * 8;
                *(float2*)(fout + (size_t)r * 1024 + cx)       = make_float2(acc[i][j][0], acc[i][j][1]);
                *(float2*)(fout + (size_t)(r + 8) * 1024 + cx) = make_float2(acc[i][j][2], acc[i][j][3]);
            }
    }
}

__global__ __launch_bounds__(256, 2)
void proj_qkv_cp() {
    if (blockIdx.z == 0)
        gemm_cp_body(g_x16, g_Wqh16, g_Wql16, 0, g_Qh, nullptr, g_qn);
    else if (blockIdx.z == 1)
        gemm_cp_body(g_x16, g_Wkh16, g_Wkl16, 1, g_Kh, nullptr, g_kn);
    else
        gemm_cp_body(g_x16, g_Wvh16, g_Wvl16, 2, g_Vh, nullptr, nullptr);
}

__global__ __launch_bounds__(256, 2)
void out_proj_cp(float* __restrict__ out) {
    gemm_cp_body(g_Of, g_Woh16, g_Wol16, 3, nullptr, out, nullptr);
}

// ---------------------------------------------------------------------------
// Hyperbolic flash attention — 128-wide KV staging (2-stage), hoisted Q
// fragments, conditional max-correction. Math identical to R11.
// ---------------------------------------------------------------------------
#define AST0  16384                        // Q
#define ASTSZ 32768                        // K(16K) | V(16K) per 128-row tile
#define AKN   (AST0 + 2 * ASTSZ)           // 81920
#define ASMEM (AKN + 2 * 512)              // 82944

__global__ __launch_bounds__(256, 2)
void attn_cp(const float* __restrict__ lc_p, const float* __restrict__ lb_p) {
    extern __shared__ char smem[];
    const uint32_t SB = smem_u32(smem);
    const uint32_t QS = SB;

    const int t = threadIdx.x;
    const int L = t & 31;
    const int w = t >> 5;
    const int bh = blockIdx.y;
    const int b  = bh >> 4, h = bh & 15;
    const int qx = (int)gridDim.x - 1 - (int)blockIdx.x;
    const int qrow0 = qx * 128;
    const int wr0 = qrow0 + w * 16;

    const float cc = log1pf(expf(*lc_p));
    const float bb = log1pf(expf(*lb_p)) + 0.5f;
    const float bL2E = bb * 1.4426950408889634f;
    const float C0 = -bL2E * 0.693f;
    const float C1 = -bL2E * 0.34657359f;
    const float C2 = -bL2E * cc * 0.25f;

    const int n2 = qx + 1;                 // 128-wide tiles

    auto issueKV = [&](int kt2) {
        const int k0 = kt2 * 128;
        const uint32_t sb = SB + AST0 + (uint32_t)(kt2 & 1) * ASTSZ;
#pragma unroll
        for (int u = 0; u < 8; u++) {
            int idx = t + 256 * u;                    // 0..2047
            int tile = idx >> 10, r = (idx >> 3) & 127, ch = idx & 7;
            const __half* base = tile ? g_Vh : g_Kh;
            const void* src = base + (size_t)(b * Nv + k0 + r) * Dv + h * Dhv + ch * 8;
            cp16(sb + tile * 16384 + r * 128 + ((ch ^ (r & 7)) << 4), src);
        }
        if (t < 32)
            cp16(SB + AKN + (kt2 & 1) * 512 + t * 16, g_kn + (size_t)bh * Nv + k0 + t * 4);
        CP_COMMIT();
    };

    // prologue: Q bundled into group 0
#pragma unroll
    for (int u = 0; u < 4; u++) {
        int idx = t + 256 * u;
        int r = idx >> 3, ch = idx & 7;
        const void* src = g_Qh + (size_t)(b * Nv + qrow0 + r) * Dv + h * Dhv + ch * 8;
        cp16(QS + r * 128 + ((ch ^ (r & 7)) << 4), src);
    }
    issueKV(0);
    if (n2 > 1) issueKV(1);

    const float qn0 = g_qn[(size_t)bh * Nv + wr0 + (L >> 2)];
    const float qn1 = g_qn[(size_t)bh * Nv + wr0 + (L >> 2) + 8];
    const float cq0 = fmaf(C2, qn0, C0);
    const float cq1 = fmaf(C2, qn1, C0);

    float o[8][4];
#pragma unroll
    for (int j = 0; j < 8; j++)
#pragma unroll
        for (int e = 0; e < 4; e++) o[j][e] = 0.0f;
    float m0r = -1e30f, m1r = -1e30f, l0r = 0.0f, l1r = 0.0f;

    uint32_t aq[4][4];                     // hoisted Q fragments (kt-invariant)
    bool aqld = false;
    const int arow = w * 16 + (L & 15);

#pragma unroll 1
    for (int kt2 = 0; kt2 < n2; kt2++) {
        if (kt2 + 1 < n2) { CP_WAIT(1); } else { CP_WAIT(0); }
        __syncthreads();
        if (!aqld) {
#pragma unroll
            for (int ks = 0; ks < 4; ks++) {
                int ch = 2 * ks + (L >> 4);
                LDSM4(aq[ks][0], aq[ks][1], aq[ks][2], aq[ks][3],
                      QS + arow * 128 + ((ch ^ (arow & 7)) << 4));
            }
            aqld = true;
        }
        const uint32_t sbase = SB + AST0 + (uint32_t)(kt2 & 1) * ASTSZ;

#pragma unroll 1
        for (int half = 0; half < 2; half++) {
            const int k0 = kt2 * 128 + half * 64;
            if (k0 > wr0 + 15) break;
            const uint32_t sbK = sbase + (uint32_t)half * 8192;
            const uint32_t sbV = sbase + 16384 + (uint32_t)half * 8192;
            const float* kn_s = (const float*)(smem + AKN + (kt2 & 1) * 512 + half * 256);

            // ---- S = Q K^T (fp16 mma, hoisted aq) ----
            float sc[8][4];
#pragma unroll
            for (int j = 0; j < 8; j++)
#pragma unroll
                for (int e = 0; e < 4; e++) sc[j][e] = 0.0f;
#pragma unroll
            for (int ks = 0; ks < 4; ks++) {
#pragma unroll
                for (int jn = 0; jn < 4; jn++) {
                    uint32_t bk[4];
                    int brow = jn * 16 + ((L >> 4) & 1) * 8 + (L & 7);
                    int ch = 2 * ks + ((L >> 3) & 1);
                    LDSM4(bk[0], bk[1], bk[2], bk[3], sbK + brow * 128 + ((ch ^ (brow & 7)) << 4));
                    mma_f16(sc[2 * jn],     aq[ks], bk[0], bk[1]);
                    mma_f16(sc[2 * jn + 1], aq[ks], bk[2], bk[3]);
                }
            }

            // ---- distance -> scores ----
            const bool need_mask = (k0 + 63 > wr0);
            float vm0 = -1e30f, vm1 = -1e30f;
            if (!need_mask) {
                float damin = 1e30f;
#pragma unroll
                for (int j = 0; j < 8; j++) {
                    float2 kn2 = *(const float2*)(kn_s + 8 * j + 2 * (L & 3));
                    float d0 = fmaf(-2.0f, sc[j][0], qn0 + kn2.x);
                    float d1 = fmaf(-2.0f, sc[j][1], qn0 + kn2.y);
                    float d2 = fmaf(-2.0f, sc[j][2], qn1 + kn2.x);
                    float d3 = fmaf(-2.0f, sc[j][3], qn1 + kn2.y);
                    damin = fminf(damin, fminf(fminf(d0, d1), fminf(d2, d3)));
                    float s0 = fmaf(C1, f_lg2(d0), fmaf(C2, kn2.x, cq0));
                    float s1 = fmaf(C1, f_lg2(d1), fmaf(C2, kn2.y, cq0));
                    float s2v = fmaf(C1, f_lg2(d2), fmaf(C2, kn2.x, cq1));
                    float s3 = fmaf(C1, f_lg2(d3), fmaf(C2, kn2.y, cq1));
                    sc[j][0] = s0; sc[j][1] = s1; sc[j][2] = s2v; sc[j][3] = s3;
                    vm0 = fmaxf(vm0, fmaxf(s0, s1));
                    vm1 = fmaxf(vm1, fmaxf(s2v, s3));
                }
                if (damin < 4.0f) {
                    vm0 = -1e30f; vm1 = -1e30f;
                    const float invC1 = 1.0f / C1;
#pragma unroll
                    for (int j = 0; j < 8; j++) {
                        float2 kn2 = *(const float2*)(kn_s + 8 * j + 2 * (L & 3));
#pragma unroll
                        for (int e = 0; e < 4; e++) {
                            float qn = (e < 2) ? qn0 : qn1;
                            float cq = (e < 2) ? cq0 : cq1;
                            float kn = (e & 1) ? kn2.y : kn2.x;
                            float base = fmaf(C2, kn, cq);
                            float da = f_ex2((sc[j][e] - base) * invC1);
                            float s2 = sc[j][e];
                            if (!(da > 4.0f)) {
                                float ns = qn + kn;
                                float ed = f_sqrt(fmaxf(da, 0.0f) + 1e-8f);
                                float dist;
                                if (ed < 0.1f) {
                                    float cn = cc * ns;
                                    dist = ed * (1.0f + 0.5f * cn + 0.125f * cn * cn);
                                } else if (ed > 2.0f) {
                                    dist = 0.693f + 0.6931472f * f_lg2(ed + 1e-8f) + cc * ns * 0.25f;
                                } else {
                                    dist = ed * f_sqrt(1.0f + cc * ns);
                                }
                                s2 = -bL2E * dist;
                            }
                            sc[j][e] = s2;
                            if (e < 2) vm0 = fmaxf(vm0, s2); else vm1 = fmaxf(vm1, s2);
                        }
                    }
                }
            } else {
                const int rg0 = wr0 + (L >> 2), rg1 = rg0 + 8;
#pragma unroll
                for (int j = 0; j < 8; j++) {
                    float2 kn2 = *(const float2*)(kn_s + 8 * j + 2 * (L & 3));
                    const int cg = k0 + 8 * j + 2 * (L & 3);
#pragma unroll
                    for (int e = 0; e < 4; e++) {
                        float qn = (e < 2) ? qn0 : qn1;
                        float kn = (e & 1) ? kn2.y : kn2.x;
                        float ns = qn + kn;
                        float da = fmaxf(fmaf(-2.0f, sc[j][e], ns), 0.0f) + 1e-8f;
                        float s2;
                        if (da > 4.0f) {
                            s2 = fmaf(C1, f_lg2(da), fmaf(C2, ns, C0));
                        } else {
                            float ed = f_sqrt(da);
                            float dist;
                            if (ed < 0.1f) {
                                float cn = cc * ns;
                                dist = ed * (1.0f + 0.5f * cn + 0.125f * cn * cn);
                            } else if (ed > 2.0f) {
                                dist = 0.693f + 0.6931472f * f_lg2(ed + 1e-8f) + cc * ns * 0.25f;
                            } else {
                                dist = ed * f_sqrt(1.0f + cc * ns);
                            }
                            s2 = -bL2E * dist;
                        }
                        int rowg = (e < 2) ? rg0 : rg1;
                        if (cg + (e & 1) > rowg) s2 = -1e30f;
                        sc[j][e] = s2;
                        if (e < 2) vm0 = fmaxf(vm0, s2); else vm1 = fmaxf(vm1, s2);
                    }
                }
            }
            vm0 = fmaxf(vm0, __shfl_xor_sync(0xffffffffu, vm0, 1));
            vm0 = fmaxf(vm0, __shfl_xor_sync(0xffffffffu, vm0, 2));
            vm1 = fmaxf(vm1, __shfl_xor_sync(0xffffffffu, vm1, 1));
            vm1 = fmaxf(vm1, __shfl_xor_sync(0xffffffffu, vm1, 2));

            // conditional max-correction (exact: skip when corr == 1)
            if (vm0 > m0r) {
                float corr0 = f_ex2(m0r - vm0);
                m0r = vm0;
                l0r *= corr0;
#pragma unroll
                for (int j = 0; j < 8; j++) { o[j][0] *= corr0; o[j][1] *= corr0; }
            }
            if (vm1 > m1r) {
                float corr1 = f_ex2(m1r - vm1);
                m1r = vm1;
                l1r *= corr1;
#pragma unroll
                for (int j = 0; j < 8; j++) { o[j][2] *= corr1; o[j][3] *= corr1; }
            }

            float rs0 = 0.0f, rs1 = 0.0f;
#pragma unroll
            for (int j = 0; j < 8; j++) {
                float p0 = f_ex2(sc[j][0] - m0r);
                float p1 = f_ex2(sc[j][1] - m0r);
                float p2 = f_ex2(sc[j][2] - m1r);
                float p3 = f_ex2(sc[j][3] - m1r);
                sc[j][0] = p0; sc[j][1] = p1; sc[j][2] = p2; sc[j][3] = p3;
                rs0 += p0 + p1; rs1 += p2 + p3;
            }
            rs0 += __shfl_xor_sync(0xffffffffu, rs0, 1);
            rs0 += __shfl_xor_sync(0xffffffffu, rs0, 2);
            rs1 += __shfl_xor_sync(0xffffffffu, rs1, 1);
            rs1 += __shfl_xor_sync(0xffffffffu, rs1, 2);
            l0r += rs0;
            l1r += rs1;

            // ---- PV: o += Ph*Vh ----
#pragma unroll
            for (int ks = 0; ks < 4; ks++) {
                const int j0 = 2 * ks, j1 = 2 * ks + 1;
                uint32_t aph[4];
                aph[0] = pack_h2(sc[j0][0], sc[j0][1]);
                aph[1] = pack_h2(sc[j0][2], sc[j0][3]);
                aph[2] = pack_h2(sc[j1][0], sc[j1][1]);
                aph[3] = pack_h2(sc[j1][2], sc[j1][3]);
                const int krow = 16 * ks + (L & 15);
#pragma unroll
                for (int jd = 0; jd < 4; jd++) {
                    int ch = 2 * jd + (L >> 4);
                    uint32_t voff = (uint32_t)(krow * 128 + ((ch ^ (krow & 7)) << 4));
                    uint32_t vhf[4];
                    LDSM4T(vhf[0], vhf[1], vhf[2], vhf[3], sbV + voff);
                    mma_f16(o[2 * jd],     aph, vhf[0], vhf[1]);
                    mma_f16(o[2 * jd + 1], aph, vhf[2], vhf[3]);
                }
            }
        }
        __syncthreads();
        if (kt2 + 2 < n2) issueKV(kt2 + 2);
    }

    // ---- epilogue: O normalized, single fp16 ----
    const float inv0 = 1.0f / l0r, inv1 = 1.0f / l1r;
    const size_t base0 = (size_t)(b * Nv + wr0 + (L >> 2)) * Dv + h * Dhv + 2 * (L & 3);
    const size_t base1 = base0 + 8 * (size_t)Dv;
#pragma unroll
    for (int j = 0; j < 8; j++) {
        *(uint32_t*)(g_Of + base0 + 8 * j) = pack_h2(o[j][0] * inv0, o[j][1] * inv0);
        *(uint32_t*)(g_Of + base1 + 8 * j) = pack_h2(o[j][2] * inv1, o[j][3] * inv1);
    }
}

// ---------------------------------------------------------------------------
// Launch
// ---------------------------------------------------------------------------
extern "C" void kernel_launch(void* const* d_in, const int* in_sizes, int n_in,
                              void* d_out, int out_size) {
    const float* x  = (const float*)d_in[0];
    const float* Wq = (const float*)d_in[1];
    const float* Wk = (const float*)d_in[2];
    const float* Wv = (const float*)d_in[3];
    const float* Wo = (const float*)d_in[4];
    const float* lc = (const float*)d_in[5];
    const float* lb = (const float*)d_in[6];
    float* out = (float*)d_out;

    cudaFuncSetAttribute(proj_qkv_cp, cudaFuncAttributeMaxDynamicSharedMemorySize, GEMM_SMEM);
    cudaFuncSetAttribute(out_proj_cp, cudaFuncAttributeMaxDynamicSharedMemorySize, GEMM_SMEM);
    cudaFuncSetAttribute(attn_cp,     cudaFuncAttributeMaxDynamicSharedMemorySize, ASMEM);

    prep_split<<<dim3(4096, 1, 5), 256>>>(x, Wq, Wk, Wv, Wo);
    proj_qkv_cp<<<dim3(8, 32, 3), 256, GEMM_SMEM>>>();
    attn_cp<<<dim3(Nv / 128, Bv * Hv), 256, ASMEM>>>(lc, lb);
    out_proj_cp<<<dim3(8, 32), 256, GEMM_SMEM>>>(out);
}

// round 13
// speedup vs baseline: 1.0582x; 1.0582x over previous
#include <cuda_runtime.h>
#include <cuda_fp16.h>
#include <math.h>
#include <stdint.h>

#define Bv 2
#define Nv 2048
#define Dv 1024
#define Hv 16
#define Dhv 64
#define Mrows (Bv * Nv)   // 4096

// ---------------------------------------------------------------------------
// Scratch (fp16 split formats)
// ---------------------------------------------------------------------------
__device__ __half g_x16[Mrows * Dv];
__device__ __half g_Wqh16[Dv * Dv], g_Wql16[Dv * Dv];
__device__ __half g_Wkh16[Dv * Dv], g_Wkl16[Dv * Dv];
__device__ __half g_Wvh16[Dv * Dv], g_Wvl16[Dv * Dv];
__device__ __half g_Woh16[Dv * Dv], g_Wol16[Dv * Dv];
__device__ __half g_Qh[Mrows * Dv], g_Kh[Mrows * Dv];
__device__ __half g_Vh[Mrows * Dv];
__device__ __half g_Of[Mrows * Dv];
__device__ float  g_qn[Bv * Hv * Nv], g_kn[Bv * Hv * Nv];

// ---------------------------------------------------------------------------
// Helpers (plain-sm_100-safe PTX only)
// ---------------------------------------------------------------------------
__device__ __forceinline__ uint32_t smem_u32(const void* p) {
    uint32_t a;
    asm("{ .reg .u64 t; cvta.to.shared.u64 t, %1; cvt.u32.u64 %0, t; }" : "=r"(a) : "l"(p));
    return a;
}
__device__ __forceinline__ void cp16(uint32_t dst, const void* src) {
    asm volatile("cp.async.cg.shared.global [%0], [%1], 16;" :: "r"(dst), "l"(src) : "memory");
}
#define CP_COMMIT() asm volatile("cp.async.commit_group;" ::: "memory")
#define CP_WAIT(n)  asm volatile("cp.async.wait_group %0;" :: "n"(n) : "memory")

#define LDSM4(r0, r1, r2, r3, addr) \
    asm volatile("ldmatrix.sync.aligned.m8n8.x4.shared.b16 {%0,%1,%2,%3}, [%4];" \
        : "=r"(r0), "=r"(r1), "=r"(r2), "=r"(r3) : "r"(addr))
#define LDSM4T(r0, r1, r2, r3, addr) \
    asm volatile("ldmatrix.sync.aligned.m8n8.x4.trans.shared.b16 {%0,%1,%2,%3}, [%4];" \
        : "=r"(r0), "=r"(r1), "=r"(r2), "=r"(r3) : "r"(addr))

__device__ __forceinline__ void mma_f16(float* d, const uint32_t* a, uint32_t b0, uint32_t b1) {
    asm volatile("mma.sync.aligned.m16n8k16.row.col.f32.f16.f16.f32 "
        "{%0,%1,%2,%3}, {%4,%5,%6,%7}, {%8,%9}, {%0,%1,%2,%3};"
        : "+f"(d[0]), "+f"(d[1]), "+f"(d[2]), "+f"(d[3])
        : "r"(a[0]), "r"(a[1]), "r"(a[2]), "r"(a[3]), "r"(b0), "r"(b1));
}

__device__ __forceinline__ uint32_t pack_h2(float lo, float hi) {
    __half2 h = __floats2half2_rn(lo, hi);
    return *(uint32_t*)&h;
}
__device__ __forceinline__ void hsplit2(float a, float b, uint32_t& h, uint32_t& l) {
    h = pack_h2(a, b);
    float2 f = __half22float2(*(__half2*)&h);
    l = pack_h2(a - f.x, b - f.y);
}

__device__ __forceinline__ float f_lg2(float x) { float r; asm("lg2.approx.f32 %0, %1;" : "=f"(r) : "f"(x)); return r; }
__device__ __forceinline__ float f_ex2(float x) { float r; asm("ex2.approx.f32 %0, %1;" : "=f"(r) : "f"(x)); return r; }
__device__ __forceinline__ float f_sqrt(float x){ float r; asm("sqrt.approx.f32 %0, %1;" : "=f"(r) : "f"(x)); return r; }

// ---------------------------------------------------------------------------
// Prep: x -> fp16; each W -> fp16 hi/lo
// ---------------------------------------------------------------------------
__global__ void prep_split(const float* __restrict__ x, const float* __restrict__ Wq,
                           const float* __restrict__ Wk, const float* __restrict__ Wv,
                           const float* __restrict__ Wo) {
    int i = (blockIdx.x * 256 + threadIdx.x) * 4;
    if (blockIdx.z == 0) {
        if (i >= Mrows * Dv) return;
        float4 v = *(const float4*)(x + i);
        uint32_t h01 = pack_h2(v.x, v.y), h23 = pack_h2(v.z, v.w);
        *(uint32_t*)(g_x16 + i) = h01; *(uint32_t*)(g_x16 + i + 2) = h23;
        return;
    }
    const float* src; __half *hi, *lo;
    switch (blockIdx.z) {
        case 1:  src = Wq; hi = g_Wqh16; lo = g_Wql16; break;
        case 2:  src = Wk; hi = g_Wkh16; lo = g_Wkl16; break;
        case 3:  src = Wv; hi = g_Wvh16; lo = g_Wvl16; break;
        default: src = Wo; hi = g_Woh16; lo = g_Wol16; break;
    }
    if (i >= Dv * Dv) return;
    float4 v = *(const float4*)(src + i);
    uint32_t h01, l01, h23, l23;
    hsplit2(v.x, v.y, h01, l01);
    hsplit2(v.z, v.w, h23, l23);
    *(uint32_t*)(hi + i) = h01; *(uint32_t*)(hi + i + 2) = h23;
    *(uint32_t*)(lo + i) = l01; *(uint32_t*)(lo + i + 2) = l23;
}

// ---------------------------------------------------------------------------
// 2xFP16 GEMM (R11-proven, unchanged): D = Ah @ (Wh + Wl)^T.
// ---------------------------------------------------------------------------
#define GSTAGE    24576
#define GEMM_SMEM (3 * GSTAGE)

__device__ __forceinline__ void gemm_cp_body(
    const __half* __restrict__ Ah,
    const __half* __restrict__ Wh, const __half* __restrict__ Wl,
    int mode, __half* outH, float* fout, float* nrm_out)
{
    extern __shared__ char smem[];
    const uint32_t SB = smem_u32(smem);
    const int t = threadIdx.x, L = t & 31, wid = t >> 5;
    const int wm = wid >> 2, wn = wid & 3;
    const int m0 = blockIdx.y * 128, n0 = blockIdx.x * 128;

    auto issue = [&](int kc) {
        const int k0 = kc * 32;
        const uint32_t sbase = SB + (uint32_t)(kc % 3) * GSTAGE;
#pragma unroll
        for (int u = 0; u < 6; u++) {
            int idx = t + 256 * u;
            int tile = idx >> 9, r = (idx >> 2) & 127, ch = idx & 3;
            const __half* base = (tile == 0) ? Ah : (tile == 1) ? Wh : Wl;
            int grow = ((tile == 0) ? m0 : n0) + r;
            const void* src = base + (size_t)grow * 1024 + k0 + ch * 8;
            cp16(sbase + tile * 8192 + r * 64 + (((ch ^ ((r >> 1) & 3)) << 4)), src);
        }
        CP_COMMIT();
    };

    issue(0);
    issue(1);

    const int arow = wm * 64 + (L & 15);
    const int brow = wn * 32 + ((L >> 4) & 1) * 8 + (L & 7);
    const uint32_t aRowOff = (uint32_t)(arow * 64);
    const uint32_t bhOff = (uint32_t)(8192 + brow * 64);
    const uint32_t blOff = (uint32_t)(16384 + brow * 64);
    const uint32_t aXr = (uint32_t)((arow >> 1) & 3);
    const uint32_t bXr = (uint32_t)((brow >> 1) & 3);

    float acc[4][4][4];
#pragma unroll
    for (int i = 0; i < 4; i++)
#pragma unroll
        for (int j = 0; j < 4; j++)
#pragma unroll
            for (int r = 0; r < 4; r++) acc[i][j][r] = 0.0f;

#pragma unroll 1
    for (int kc = 0; kc < 32; kc++) {
        if (kc < 31) { CP_WAIT(1); } else { CP_WAIT(0); }
        __syncthreads();
        if (kc + 2 < 32) issue(kc + 2);
        const uint32_t sb = SB + (uint32_t)(kc % 3) * GSTAGE;
#pragma unroll
        for (int js = 0; js < 2; js++) {
            const uint32_t achunk = (uint32_t)((((2 * js + (L >> 4)) ^ aXr) << 4));
            const uint32_t bchunk = (uint32_t)((((2 * js + ((L >> 3) & 1)) ^ bXr) << 4));
            uint32_t ah[4][4];
#pragma unroll
            for (int i = 0; i < 4; i++)
                LDSM4(ah[i][0], ah[i][1], ah[i][2], ah[i][3], sb + aRowOff + i * 1024 + achunk);
#pragma unroll
            for (int jp = 0; jp < 2; jp++) {
                uint32_t bh[4], bl[4];
                LDSM4(bh[0], bh[1], bh[2], bh[3], sb + bhOff + jp * 1024 + bchunk);
                LDSM4(bl[0], bl[1], bl[2], bl[3], sb + blOff + jp * 1024 + bchunk);
#pragma unroll
                for (int i = 0; i < 4; i++) {
                    mma_f16(acc[i][jp * 2],     ah[i], bh[0], bh[1]);
                    mma_f16(acc[i][jp * 2 + 1], ah[i], bh[2], bh[3]);
                }
#pragma unroll
                for (int i = 0; i < 4; i++) {
                    mma_f16(acc[i][jp * 2],     ah[i], bl[0], bl[1]);
                    mma_f16(acc[i][jp * 2 + 1], ah[i], bl[2], bl[3]);
                }
            }
        }
    }

    const int rb = m0 + wm * 64 + (L >> 2);
    const int cb = n0 + wn * 32 + (L & 3) * 2;

    if (mode <= 1) {
        float p0s[4], p1s[4];
#pragma unroll
        for (int i = 0; i < 4; i++) {
            float s0 = 0.0f, s1 = 0.0f;
#pragma unroll
            for (int j = 0; j < 4; j++) {
                const int r = rb + i * 16, c = cb + j * 8;
                *(__half2*)(outH + (size_t)r * 1024 + c)       = __floats2half2_rn(acc[i][j][0], acc[i][j][1]);
                *(__half2*)(outH + (size_t)(r + 8) * 1024 + c) = __floats2half2_rn(acc[i][j][2], acc[i][j][3]);
                s0 = fmaf(acc[i][j][0], acc[i][j][0], fmaf(acc[i][j][1], acc[i][j][1], s0));
                s1 = fmaf(acc[i][j][2], acc[i][j][2], fmaf(acc[i][j][3], acc[i][j][3], s1));
            }
            s0 += __shfl_xor_sync(0xffffffffu, s0, 1);
            s0 += __shfl_xor_sync(0xffffffffu, s0, 2);
            s1 += __shfl_xor_sync(0xffffffffu, s1, 1);
            s1 += __shfl_xor_sync(0xffffffffu, s1, 2);
            p0s[i] = s0; p1s[i] = s1;
        }
        __syncthreads();
        float* part = (float*)smem;
        if ((L & 3) == 0) {
#pragma unroll
            for (int i = 0; i < 4; i++) {
                int r0 = wm * 64 + (L >> 2) + i * 16;
                part[r0 * 4 + wn] = p0s[i];
                part[(r0 + 8) * 4 + wn] = p1s[i];
            }
        }
        __syncthreads();
        {
            int row = t >> 1, ph = t & 1;
            float s = part[row * 4 + 2 * ph] + part[row * 4 + 2 * ph + 1];
            int grow = m0 + row, head = (n0 >> 6) + ph;
            int b = grow >> 11, n = grow & 2047;
            nrm_out[((b << 4) + head) * Nv + n] = s;
        }
    } else if (mode == 2) {
#pragma unroll
        for (int i = 0; i < 4; i++)
#pragma unroll
            for (int j = 0; j < 4; j++) {
                const int r = rb + i * 16, c = cb + j * 8;
                *(__half2*)(outH + (size_t)r * 1024 + c)       = __floats2half2_rn(acc[i][j][0], acc[i][j][1]);
                *(__half2*)(outH + (size_t)(r + 8) * 1024 + c) = __floats2half2_rn(acc[i][j][2], acc[i][j][3]);
            }
    } else {
#pragma unroll
        for (int i = 0; i < 4; i++)
#pragma unroll
            for (int j = 0; j < 4; j++) {
                const int r = rb + i * 16, cx = cb + j * 8;
                *(float2*)(fout + (size_t)r * 1024 + cx)       = make_float2(acc[i][j][0], acc[i][j][1]);
                *(float2*)(fout + (size_t)(r + 8) * 1024 + cx) = make_float2(acc[i][j][2], acc[i][j][3]);
            }
    }
}

__global__ __launch_bounds__(256, 2)
void proj_qkv_cp() {
    if (blockIdx.z == 0)
        gemm_cp_body(g_x16, g_Wqh16, g_Wql16, 0, g_Qh, nullptr, g_qn);
    else if (blockIdx.z == 1)
        gemm_cp_body(g_x16, g_Wkh16, g_Wkl16, 1, g_Kh, nullptr, g_kn);
    else
        gemm_cp_body(g_x16, g_Wvh16, g_Wvl16, 2, g_Vh, nullptr, nullptr);
}

__global__ __launch_bounds__(256, 2)
void out_proj_cp(float* __restrict__ out) {
    gemm_cp_body(g_Of, g_Woh16, g_Wol16, 3, nullptr, out, nullptr);
}

// ---------------------------------------------------------------------------
// Hyperbolic flash attention — R11 structure (64-wide, 3-stage ring) with ONE
// change: conditional max-correction (exact skip when running max unchanged).
// ---------------------------------------------------------------------------
#define AST0  16384
#define ASTSZ 16384
#define AKN   (AST0 + 3 * ASTSZ)          // 65536
#define ASMEM (AKN + 3 * 256)             // 66304

__global__ __launch_bounds__(256, 2)
void attn_cp(const float* __restrict__ lc_p, const float* __restrict__ lb_p) {
    extern __shared__ char smem[];
    const uint32_t SB = smem_u32(smem);
    const uint32_t QS = SB;

    const int t = threadIdx.x;
    const int L = t & 31;
    const int w = t >> 5;
    const int bh = blockIdx.y;
    const int b  = bh >> 4, h = bh & 15;
    const int qx = (int)gridDim.x - 1 - (int)blockIdx.x;
    const int qrow0 = qx * 128;
    const int wr0 = qrow0 + w * 16;

    const float cc = log1pf(expf(*lc_p));
    const float bb = log1pf(expf(*lb_p)) + 0.5f;
    const float bL2E = bb * 1.4426950408889634f;
    const float C0 = -bL2E * 0.693f;
    const float C1 = -bL2E * 0.34657359f;
    const float C2 = -bL2E * cc * 0.25f;

    const int n_kt = 2 * qx + 2;

    auto issueKV = [&](int kt) {
        const int k0 = kt * 64;
        const uint32_t sb = SB + AST0 + (uint32_t)(kt % 3) * ASTSZ;
#pragma unroll
        for (int u = 0; u < 4; u++) {
            int idx = t + 256 * u;
            int tile = idx >> 9, r = (idx >> 3) & 63, ch = idx & 7;
            const __half* base = (tile == 0) ? g_Kh : g_Vh;
            const void* src = base + (size_t)(b * Nv + k0 + r) * Dv + h * Dhv + ch * 8;
            cp16(sb + tile * 8192 + r * 128 + ((ch ^ (r & 7)) << 4), src);
        }
        if (t < 16)
            cp16(SB + AKN + (kt % 3) * 256 + t * 16, g_kn + (size_t)bh * Nv + k0 + t * 4);
        CP_COMMIT();
    };

#pragma unroll
    for (int u = 0; u < 4; u++) {
        int idx = t + 256 * u;
        int r = idx >> 3, ch = idx & 7;
        const void* src = g_Qh + (size_t)(b * Nv + qrow0 + r) * Dv + h * Dhv + ch * 8;
        cp16(QS + r * 128 + ((ch ^ (r & 7)) << 4), src);
    }
    issueKV(0);
    if (n_kt > 1) issueKV(1);

    const float qn0 = g_qn[(size_t)bh * Nv + wr0 + (L >> 2)];
    const float qn1 = g_qn[(size_t)bh * Nv + wr0 + (L >> 2) + 8];
    const float cq0 = fmaf(C2, qn0, C0);
    const float cq1 = fmaf(C2, qn1, C0);

    float o[8][4];
#pragma unroll
    for (int j = 0; j < 8; j++)
#pragma unroll
        for (int e = 0; e < 4; e++) o[j][e] = 0.0f;
    float m0r = -1e30f, m1r = -1e30f, l0r = 0.0f, l1r = 0.0f;

#pragma unroll 1
    for (int kt = 0; kt < n_kt; kt++) {
        if (kt + 1 < n_kt) { CP_WAIT(1); } else { CP_WAIT(0); }
        __syncthreads();
        if (kt + 2 < n_kt) issueKV(kt + 2);
        const int k0 = kt * 64;
        const uint32_t sb = SB + AST0 + (uint32_t)(kt % 3) * ASTSZ;
        const float* kn_s = (const float*)(smem + AKN + (kt % 3) * 256);

        if (k0 <= wr0 + 15) {
            // ---- S = Q K^T (fp16 mma) ----
            float sc[8][4];
#pragma unroll
            for (int j = 0; j < 8; j++)
#pragma unroll
                for (int e = 0; e < 4; e++) sc[j][e] = 0.0f;
#pragma unroll
            for (int ks = 0; ks < 4; ks++) {
                uint32_t aq[4];
                {
                    int arow = w * 16 + (L & 15);
                    int ch = 2 * ks + (L >> 4);
                    LDSM4(aq[0], aq[1], aq[2], aq[3], QS + arow * 128 + ((ch ^ (arow & 7)) << 4));
                }
#pragma unroll
                for (int jn = 0; jn < 4; jn++) {
                    uint32_t bk[4];
                    int brow = jn * 16 + ((L >> 4) & 1) * 8 + (L & 7);
                    int ch = 2 * ks + ((L >> 3) & 1);
                    LDSM4(bk[0], bk[1], bk[2], bk[3], sb + brow * 128 + ((ch ^ (brow & 7)) << 4));
                    mma_f16(sc[2 * jn],     aq, bk[0], bk[1]);
                    mma_f16(sc[2 * jn + 1], aq, bk[2], bk[3]);
                }
            }

            // ---- distance -> scores ----
            const bool need_mask = (k0 + 63 > wr0);
            float vm0 = -1e30f, vm1 = -1e30f;
            if (!need_mask) {
                float damin = 1e30f;
#pragma unroll
                for (int j = 0; j < 8; j++) {
                    float2 kn2 = *(const float2*)(kn_s + 8 * j + 2 * (L & 3));
                    float d0 = fmaf(-2.0f, sc[j][0], qn0 + kn2.x);
                    float d1 = fmaf(-2.0f, sc[j][1], qn0 + kn2.y);
                    float d2 = fmaf(-2.0f, sc[j][2], qn1 + kn2.x);
                    float d3 = fmaf(-2.0f, sc[j][3], qn1 + kn2.y);
                    damin = fminf(damin, fminf(fminf(d0, d1), fminf(d2, d3)));
                    float s0 = fmaf(C1, f_lg2(d0), fmaf(C2, kn2.x, cq0));
                    float s1 = fmaf(C1, f_lg2(d1), fmaf(C2, kn2.y, cq0));
                    float s2v = fmaf(C1, f_lg2(d2), fmaf(C2, kn2.x, cq1));
                    float s3 = fmaf(C1, f_lg2(d3), fmaf(C2, kn2.y, cq1));
                    sc[j][0] = s0; sc[j][1] = s1; sc[j][2] = s2v; sc[j][3] = s3;
                    vm0 = fmaxf(vm0, fmaxf(s0, s1));
                    vm1 = fmaxf(vm1, fmaxf(s2v, s3));
                }
                if (damin < 4.0f) {
                    vm0 = -1e30f; vm1 = -1e30f;
                    const float invC1 = 1.0f / C1;
#pragma unroll
                    for (int j = 0; j < 8; j++) {
                        float2 kn2 = *(const float2*)(kn_s + 8 * j + 2 * (L & 3));
#pragma unroll
                        for (int e = 0; e < 4; e++) {
                            float qn = (e < 2) ? qn0 : qn1;
                            float cq = (e < 2) ? cq0 : cq1;
                            float kn = (e & 1) ? kn2.y : kn2.x;
                            float base = fmaf(C2, kn, cq);
                            float da = f_ex2((sc[j][e] - base) * invC1);
                            float s2 = sc[j][e];
                            if (!(da > 4.0f)) {
                                float ns = qn + kn;
                                float ed = f_sqrt(fmaxf(da, 0.0f) + 1e-8f);
                                float dist;
                                if (ed < 0.1f) {
                                    float cn = cc * ns;
                                    dist = ed * (1.0f + 0.5f * cn + 0.125f * cn * cn);
                                } else if (ed > 2.0f) {
                                    dist = 0.693f + 0.6931472f * f_lg2(ed + 1e-8f) + cc * ns * 0.25f;
                                } else {
                                    dist = ed * f_sqrt(1.0f + cc * ns);
                                }
                                s2 = -bL2E * dist;
                            }
                            sc[j][e] = s2;
                            if (e < 2) vm0 = fmaxf(vm0, s2); else vm1 = fmaxf(vm1, s2);
                        }
                    }
                }
            } else {
                const int rg0 = wr0 + (L >> 2), rg1 = rg0 + 8;
#pragma unroll
                for (int j = 0; j < 8; j++) {
                    float2 kn2 = *(const float2*)(kn_s + 8 * j + 2 * (L & 3));
                    const int cg = k0 + 8 * j + 2 * (L & 3);
#pragma unroll
                    for (int e = 0; e < 4; e++) {
                        float qn = (e < 2) ? qn0 : qn1;
                        float kn = (e & 1) ? kn2.y : kn2.x;
                        float ns = qn + kn;
                        float da = fmaxf(fmaf(-2.0f, sc[j][e], ns), 0.0f) + 1e-8f;
                        float s2;
                        if (da > 4.0f) {
                            s2 = fmaf(C1, f_lg2(da), fmaf(C2, ns, C0));
                        } else {
                            float ed = f_sqrt(da);
                            float dist;
                            if (ed < 0.1f) {
                                float cn = cc * ns;
                                dist = ed * (1.0f + 0.5f * cn + 0.125f * cn * cn);
                            } else if (ed > 2.0f) {
                                dist = 0.693f + 0.6931472f * f_lg2(ed + 1e-8f) + cc * ns * 0.25f;
                            } else {
                                dist = ed * f_sqrt(1.0f + cc * ns);
                            }
                            s2 = -bL2E * dist;
                        }
                        int rowg = (e < 2) ? rg0 : rg1;
                        if (cg + (e & 1) > rowg) s2 = -1e30f;
                        sc[j][e] = s2;
                        if (e < 2) vm0 = fmaxf(vm0, s2); else vm1 = fmaxf(vm1, s2);
                    }
                }
            }
            vm0 = fmaxf(vm0, __shfl_xor_sync(0xffffffffu, vm0, 1));
            vm0 = fmaxf(vm0, __shfl_xor_sync(0xffffffffu, vm0, 2));
            vm1 = fmaxf(vm1, __shfl_xor_sync(0xffffffffu, vm1, 1));
            vm1 = fmaxf(vm1, __shfl_xor_sync(0xffffffffu, vm1, 2));

            // conditional max-correction (exact: corr == 1 when max unchanged)
            if (vm0 > m0r) {
                float corr0 = f_ex2(m0r - vm0);
                m0r = vm0;
                l0r *= corr0;
#pragma unroll
                for (int j = 0; j < 8; j++) { o[j][0] *= corr0; o[j][1] *= corr0; }
            }
            if (vm1 > m1r) {
                float corr1 = f_ex2(m1r - vm1);
                m1r = vm1;
                l1r *= corr1;
#pragma unroll
                for (int j = 0; j < 8; j++) { o[j][2] *= corr1; o[j][3] *= corr1; }
            }

            float rs0 = 0.0f, rs1 = 0.0f;
#pragma unroll
            for (int j = 0; j < 8; j++) {
                float p0 = f_ex2(sc[j][0] - m0r);
                float p1 = f_ex2(sc[j][1] - m0r);
                float p2 = f_ex2(sc[j][2] - m1r);
                float p3 = f_ex2(sc[j][3] - m1r);
                sc[j][0] = p0; sc[j][1] = p1; sc[j][2] = p2; sc[j][3] = p3;
                rs0 += p0 + p1; rs1 += p2 + p3;
            }
            rs0 += __shfl_xor_sync(0xffffffffu, rs0, 1);
            rs0 += __shfl_xor_sync(0xffffffffu, rs0, 2);
            rs1 += __shfl_xor_sync(0xffffffffu, rs1, 1);
            rs1 += __shfl_xor_sync(0xffffffffu, rs1, 2);
            l0r += rs0;
            l1r += rs1;

            // ---- PV: o += Ph*Vh ----
#pragma unroll
            for (int ks = 0; ks < 4; ks++) {
                const int j0 = 2 * ks, j1 = 2 * ks + 1;
                uint32_t aph[4];
                aph[0] = pack_h2(sc[j0][0], sc[j0][1]);
                aph[1] = pack_h2(sc[j0][2], sc[j0][3]);
                aph[2] = pack_h2(sc[j1][0], sc[j1][1]);
                aph[3] = pack_h2(sc[j1][2], sc[j1][3]);
                const int krow = 16 * ks + (L & 15);
#pragma unroll
                for (int jd = 0; jd < 4; jd++) {
                    int ch = 2 * jd + (L >> 4);
                    uint32_t voff = (uint32_t)(krow * 128 + ((ch ^ (krow & 7)) << 4));
                    uint32_t vhf[4];
                    LDSM4T(vhf[0], vhf[1], vhf[2], vhf[3], sb + 8192 + voff);
                    mma_f16(o[2 * jd],     aph, vhf[0], vhf[1]);
                    mma_f16(o[2 * jd + 1], aph, vhf[2], vhf[3]);
                }
            }
        }
    }

    // ---- epilogue: O normalized, single fp16 ----
    const float inv0 = 1.0f / l0r, inv1 = 1.0f / l1r;
    const size_t base0 = (size_t)(b * Nv + wr0 + (L >> 2)) * Dv + h * Dhv + 2 * (L & 3);
    const size_t base1 = base0 + 8 * (size_t)Dv;
#pragma unroll
    for (int j = 0; j < 8; j++) {
        *(uint32_t*)(g_Of + base0 + 8 * j) = pack_h2(o[j][0] * inv0, o[j][1] * inv0);
        *(uint32_t*)(g_Of + base1 + 8 * j) = pack_h2(o[j][2] * inv1, o[j][3] * inv1);
    }
}

// ---------------------------------------------------------------------------
// Launch
// ---------------------------------------------------------------------------
extern "C" void kernel_launch(void* const* d_in, const int* in_sizes, int n_in,
                              void* d_out, int out_size) {
    const float* x  = (const float*)d_in[0];
    const float* Wq = (const float*)d_in[1];
    const float* Wk = (const float*)d_in[2];
    const float* Wv = (const float*)d_in[3];
    const float* Wo = (const float*)d_in[4];
    const float* lc = (const float*)d_in[5];
    const float* lb = (const float*)d_in[6];
    float* out = (float*)d_out;

    cudaFuncSetAttribute(proj_qkv_cp, cudaFuncAttributeMaxDynamicSharedMemorySize, GEMM_SMEM);
    cudaFuncSetAttribute(out_proj_cp, cudaFuncAttributeMaxDynamicSharedMemorySize, GEMM_SMEM);
    cudaFuncSetAttribute(attn_cp,     cudaFuncAttributeMaxDynamicSharedMemorySize, ASMEM);

    prep_split<<<dim3(4096, 1, 5), 256>>>(x, Wq, Wk, Wv, Wo);
    proj_qkv_cp<<<dim3(8, 32, 3), 256, GEMM_SMEM>>>();
    attn_cp<<<dim3(Nv / 128, Bv * Hv), 256, ASMEM>>>(lc, lb);
    out_proj_cp<<<dim3(8, 32), 256, GEMM_SMEM>>>(out);
}

// round 15
// speedup vs baseline: 1.0626x; 1.0041x over previous
#include <cuda_runtime.h>
#include <cuda_fp16.h>
#include <math.h>
#include <stdint.h>

#define Bv 2
#define Nv 2048
#define Dv 1024
#define Hv 16
#define Dhv 64
#define Mrows (Bv * Nv)   // 4096

// ---------------------------------------------------------------------------
// Scratch (fp16 split formats)
// ---------------------------------------------------------------------------
__device__ __half g_x16[Mrows * Dv];
__device__ __half g_Wqh16[Dv * Dv], g_Wql16[Dv * Dv];
__device__ __half g_Wkh16[Dv * Dv], g_Wkl16[Dv * Dv];
__device__ __half g_Wvh16[Dv * Dv], g_Wvl16[Dv * Dv];
__device__ __half g_Woh16[Dv * Dv], g_Wol16[Dv * Dv];
__device__ __half g_Qh[Mrows * Dv], g_Kh[Mrows * Dv];
__device__ __half g_Vh[Mrows * Dv];
__device__ __half g_Of[Mrows * Dv];
__device__ float  g_qn[Bv * Hv * Nv], g_kn[Bv * Hv * Nv];

// ---------------------------------------------------------------------------
// Helpers (plain-sm_100-safe PTX only)
// ---------------------------------------------------------------------------
__device__ __forceinline__ uint32_t smem_u32(const void* p) {
    uint32_t a;
    asm("{ .reg .u64 t; cvta.to.shared.u64 t, %1; cvt.u32.u64 %0, t; }" : "=r"(a) : "l"(p));
    return a;
}
__device__ __forceinline__ void cp16(uint32_t dst, const void* src) {
    asm volatile("cp.async.cg.shared.global [%0], [%1], 16;" :: "r"(dst), "l"(src) : "memory");
}
#define CP_COMMIT() asm volatile("cp.async.commit_group;" ::: "memory")
#define CP_WAIT(n)  asm volatile("cp.async.wait_group %0;" :: "n"(n) : "memory")

#define LDSM4(r0, r1, r2, r3, addr) \
    asm volatile("ldmatrix.sync.aligned.m8n8.x4.shared.b16 {%0,%1,%2,%3}, [%4];" \
        : "=r"(r0), "=r"(r1), "=r"(r2), "=r"(r3) : "r"(addr))
#define LDSM4T(r0, r1, r2, r3, addr) \
    asm volatile("ldmatrix.sync.aligned.m8n8.x4.trans.shared.b16 {%0,%1,%2,%3}, [%4];" \
        : "=r"(r0), "=r"(r1), "=r"(r2), "=r"(r3) : "r"(addr))

__device__ __forceinline__ void mma_f16(float* d, const uint32_t* a, uint32_t b0, uint32_t b1) {
    asm volatile("mma.sync.aligned.m16n8k16.row.col.f32.f16.f16.f32 "
        "{%0,%1,%2,%3}, {%4,%5,%6,%7}, {%8,%9}, {%0,%1,%2,%3};"
        : "+f"(d[0]), "+f"(d[1]), "+f"(d[2]), "+f"(d[3])
        : "r"(a[0]), "r"(a[1]), "r"(a[2]), "r"(a[3]), "r"(b0), "r"(b1));
}

__device__ __forceinline__ uint32_t pack_h2(float lo, float hi) {
    __half2 h = __floats2half2_rn(lo, hi);
    return *(uint32_t*)&h;
}
__device__ __forceinline__ void hsplit2(float a, float b, uint32_t& h, uint32_t& l) {
    h = pack_h2(a, b);
    float2 f = __half22float2(*(__half2*)&h);
    l = pack_h2(a - f.x, b - f.y);
}

__device__ __forceinline__ float f_lg2(float x) { float r; asm("lg2.approx.f32 %0, %1;" : "=f"(r) : "f"(x)); return r; }
__device__ __forceinline__ float f_ex2(float x) { float r; asm("ex2.approx.f32 %0, %1;" : "=f"(r) : "f"(x)); return r; }
__device__ __forceinline__ float f_sqrt(float x){ float r; asm("sqrt.approx.f32 %0, %1;" : "=f"(r) : "f"(x)); return r; }

// ---------------------------------------------------------------------------
// Prep: x -> fp16; each W -> fp16 hi/lo
// ---------------------------------------------------------------------------
__global__ void prep_split(const float* __restrict__ x, const float* __restrict__ Wq,
                           const float* __restrict__ Wk, const float* __restrict__ Wv,
                           const float* __restrict__ Wo) {
    int i = (blockIdx.x * 256 + threadIdx.x) * 4;
    if (blockIdx.z == 0) {
        if (i >= Mrows * Dv) return;
        float4 v = *(const float4*)(x + i);
        uint32_t h01 = pack_h2(v.x, v.y), h23 = pack_h2(v.z, v.w);
        *(uint32_t*)(g_x16 + i) = h01; *(uint32_t*)(g_x16 + i + 2) = h23;
        return;
    }
    const float* src; __half *hi, *lo;
    switch (blockIdx.z) {
        case 1:  src = Wq; hi = g_Wqh16; lo = g_Wql16; break;
        case 2:  src = Wk; hi = g_Wkh16; lo = g_Wkl16; break;
        case 3:  src = Wv; hi = g_Wvh16; lo = g_Wvl16; break;
        default: src = Wo; hi = g_Woh16; lo = g_Wol16; break;
    }
    if (i >= Dv * Dv) return;
    float4 v = *(const float4*)(src + i);
    uint32_t h01, l01, h23, l23;
    hsplit2(v.x, v.y, h01, l01);
    hsplit2(v.z, v.w, h23, l23);
    *(uint32_t*)(hi + i) = h01; *(uint32_t*)(hi + i + 2) = h23;
    *(uint32_t*)(lo + i) = l01; *(uint32_t*)(lo + i + 2) = l23;
}

// ---------------------------------------------------------------------------
// 2xFP16 GEMM: D = Ah @ (Wh + Wl)^T. Stage = Ah | Wh | Wl (8KB each, SW64);
// 3-stage cp.async ring, single sync per K-chunk, 2 CTAs/SM.
// ---------------------------------------------------------------------------
#define GSTAGE    24576
#define GEMM_SMEM (3 * GSTAGE)

__device__ __forceinline__ void gemm_cp_body(
    const __half* __restrict__ Ah,
    const __half* __restrict__ Wh, const __half* __restrict__ Wl,
    int mode, __half* outH, float* fout, float* nrm_out)
{
    extern __shared__ char smem[];
    const uint32_t SB = smem_u32(smem);
    const int t = threadIdx.x, L = t & 31, wid = t >> 5;
    const int wm = wid >> 2, wn = wid & 3;
    const int m0 = blockIdx.y * 128, n0 = blockIdx.x * 128;

    auto issue = [&](int kc) {
        const int k0 = kc * 32;
        const uint32_t sbase = SB + (uint32_t)(kc % 3) * GSTAGE;
#pragma unroll
        for (int u = 0; u < 6; u++) {
            int idx = t + 256 * u;
            int tile = idx >> 9, r = (idx >> 2) & 127, ch = idx & 3;
            const __half* base = (tile == 0) ? Ah : (tile == 1) ? Wh : Wl;
            int grow = ((tile == 0) ? m0 : n0) + r;
            const void* src = base + (size_t)grow * 1024 + k0 + ch * 8;
            cp16(sbase + tile * 8192 + r * 64 + (((ch ^ ((r >> 1) & 3)) << 4)), src);
        }
        CP_COMMIT();
    };

    issue(0);
    issue(1);

    const int arow = wm * 64 + (L & 15);
    const int brow = wn * 32 + ((L >> 4) & 1) * 8 + (L & 7);
    const uint32_t aRowOff = (uint32_t)(arow * 64);
    const uint32_t bhOff = (uint32_t)(8192 + brow * 64);
    const uint32_t blOff = (uint32_t)(16384 + brow * 64);
    const uint32_t aXr = (uint32_t)((arow >> 1) & 3);
    const uint32_t bXr = (uint32_t)((brow >> 1) & 3);

    float acc[4][4][4];
#pragma unroll
    for (int i = 0; i < 4; i++)
#pragma unroll
        for (int j = 0; j < 4; j++)
#pragma unroll
            for (int r = 0; r < 4; r++) acc[i][j][r] = 0.0f;

#pragma unroll 1
    for (int kc = 0; kc < 32; kc++) {
        if (kc < 31) { CP_WAIT(1); } else { CP_WAIT(0); }
        __syncthreads();
        if (kc + 2 < 32) issue(kc + 2);
        const uint32_t sb = SB + (uint32_t)(kc % 3) * GSTAGE;
#pragma unroll
        for (int js = 0; js < 2; js++) {
            const uint32_t achunk = (uint32_t)((((2 * js + (L >> 4)) ^ aXr) << 4));
            const uint32_t bchunk = (uint32_t)((((2 * js + ((L >> 3) & 1)) ^ bXr) << 4));
            uint32_t ah[4][4];
#pragma unroll
            for (int i = 0; i < 4; i++)
                LDSM4(ah[i][0], ah[i][1], ah[i][2], ah[i][3], sb + aRowOff + i * 1024 + achunk);
#pragma unroll
            for (int jp = 0; jp < 2; jp++) {
                uint32_t bh[4], bl[4];
                LDSM4(bh[0], bh[1], bh[2], bh[3], sb + bhOff + jp * 1024 + bchunk);
                LDSM4(bl[0], bl[1], bl[2], bl[3], sb + blOff + jp * 1024 + bchunk);
#pragma unroll
                for (int i = 0; i < 4; i++) {
                    mma_f16(acc[i][jp * 2],     ah[i], bh[0], bh[1]);
                    mma_f16(acc[i][jp * 2 + 1], ah[i], bh[2], bh[3]);
                }
#pragma unroll
                for (int i = 0; i < 4; i++) {
                    mma_f16(acc[i][jp * 2],     ah[i], bl[0], bl[1]);
                    mma_f16(acc[i][jp * 2 + 1], ah[i], bl[2], bl[3]);
                }
            }
        }
    }

    const int rb = m0 + wm * 64 + (L >> 2);
    const int cb = n0 + wn * 32 + (L & 3) * 2;

    if (mode <= 1) {
        float p0s[4], p1s[4];
#pragma unroll
        for (int i = 0; i < 4; i++) {
            float s0 = 0.0f, s1 = 0.0f;
#pragma unroll
            for (int j = 0; j < 4; j++) {
                const int r = rb + i * 16, c = cb + j * 8;
                *(__half2*)(outH + (size_t)r * 1024 + c)       = __floats2half2_rn(acc[i][j][0], acc[i][j][1]);
                *(__half2*)(outH + (size_t)(r + 8) * 1024 + c) = __floats2half2_rn(acc[i][j][2], acc[i][j][3]);
                s0 = fmaf(acc[i][j][0], acc[i][j][0], fmaf(acc[i][j][1], acc[i][j][1], s0));
                s1 = fmaf(acc[i][j][2], acc[i][j][2], fmaf(acc[i][j][3], acc[i][j][3], s1));
            }
            s0 += __shfl_xor_sync(0xffffffffu, s0, 1);
            s0 += __shfl_xor_sync(0xffffffffu, s0, 2);
            s1 += __shfl_xor_sync(0xffffffffu, s1, 1);
            s1 += __shfl_xor_sync(0xffffffffu, s1, 2);
            p0s[i] = s0; p1s[i] = s1;
        }
        __syncthreads();
        float* part = (float*)smem;
        if ((L & 3) == 0) {
#pragma unroll
            for (int i = 0; i < 4; i++) {
                int r0 = wm * 64 + (L >> 2) + i * 16;
                part[r0 * 4 + wn] = p0s[i];
                part[(r0 + 8) * 4 + wn] = p1s[i];
            }
        }
        __syncthreads();
        {
            int row = t >> 1, ph = t & 1;
            float s = part[row * 4 + 2 * ph] + part[row * 4 + 2 * ph + 1];
            int grow = m0 + row, head = (n0 >> 6) + ph;
            int b = grow >> 11, n = grow & 2047;
            nrm_out[((b << 4) + head) * Nv + n] = s;
        }
    } else if (mode == 2) {
#pragma unroll
        for (int i = 0; i < 4; i++)
#pragma unroll
            for (int j = 0; j < 4; j++) {
                const int r = rb + i * 16, c = cb + j * 8;
                *(__half2*)(outH + (size_t)r * 1024 + c)       = __floats2half2_rn(acc[i][j][0], acc[i][j][1]);
                *(__half2*)(outH + (size_t)(r + 8) * 1024 + c) = __floats2half2_rn(acc[i][j][2], acc[i][j][3]);
            }
    } else {
#pragma unroll
        for (int i = 0; i < 4; i++)
#pragma unroll
            for (int j = 0; j < 4; j++) {
                const int r = rb + i * 16, cx = cb + j * 8;
                *(float2*)(fout + (size_t)r * 1024 + cx)       = make_float2(acc[i][j][0], acc[i][j][1]);
                *(float2*)(fout + (size_t)(r + 8) * 1024 + cx) = make_float2(acc[i][j][2], acc[i][j][3]);
            }
    }
}

__global__ __launch_bounds__(256, 2)
void proj_qkv_cp() {
    if (blockIdx.z == 0)
        gemm_cp_body(g_x16, g_Wqh16, g_Wql16, 0, g_Qh, nullptr, g_qn);
    else if (blockIdx.z == 1)
        gemm_cp_body(g_x16, g_Wkh16, g_Wkl16, 1, g_Kh, nullptr, g_kn);
    else
        gemm_cp_body(g_x16, g_Wvh16, g_Wvl16, 2, g_Vh, nullptr, nullptr);
}

__global__ __launch_bounds__(256, 2)
void out_proj_cp(float* __restrict__ out) {
    gemm_cp_body(g_Of, g_Woh16, g_Wol16, 3, nullptr, out, nullptr);
}

// ---------------------------------------------------------------------------
// Hyperbolic flash attention — R11-proven configuration (measured optimum):
// 64-wide tiles, 3-stage cp.async ring, single sync/tile, thin asymptotic
// score path with cold exact fallback, single-product PV, unconditional
// running-max correction.
// ---------------------------------------------------------------------------
#define AST0  16384
#define ASTSZ 16384
#define AKN   (AST0 + 3 * ASTSZ)          // 65536
#define ASMEM (AKN + 3 * 256)             // 66304

__global__ __launch_bounds__(256, 2)
void attn_cp(const float* __restrict__ lc_p, const float* __restrict__ lb_p) {
    extern __shared__ char smem[];
    const uint32_t SB = smem_u32(smem);
    const uint32_t QS = SB;

    const int t = threadIdx.x;
    const int L = t & 31;
    const int w = t >> 5;
    const int bh = blockIdx.y;
    const int b  = bh >> 4, h = bh & 15;
    const int qx = (int)gridDim.x - 1 - (int)blockIdx.x;
    const int qrow0 = qx * 128;
    const int wr0 = qrow0 + w * 16;

    const float cc = log1pf(expf(*lc_p));
    const float bb = log1pf(expf(*lb_p)) + 0.5f;
    const float bL2E = bb * 1.4426950408889634f;
    const float C0 = -bL2E * 0.693f;
    const float C1 = -bL2E * 0.34657359f;
    const float C2 = -bL2E * cc * 0.25f;

    const int n_kt = 2 * qx + 2;

    auto issueKV = [&](int kt) {
        const int k0 = kt * 64;
        const uint32_t sb = SB + AST0 + (uint32_t)(kt % 3) * ASTSZ;
#pragma unroll
        for (int u = 0; u < 4; u++) {
            int idx = t + 256 * u;
            int tile = idx >> 9, r = (idx >> 3) & 63, ch = idx & 7;
            const __half* base = (tile == 0) ? g_Kh : g_Vh;
            const void* src = base + (size_t)(b * Nv + k0 + r) * Dv + h * Dhv + ch * 8;
            cp16(sb + tile * 8192 + r * 128 + ((ch ^ (r & 7)) << 4), src);
        }
        if (t < 16)
            cp16(SB + AKN + (kt % 3) * 256 + t * 16, g_kn + (size_t)bh * Nv + k0 + t * 4);
        CP_COMMIT();
    };

#pragma unroll
    for (int u = 0; u < 4; u++) {
        int idx = t + 256 * u;
        int r = idx >> 3, ch = idx & 7;
        const void* src = g_Qh + (size_t)(b * Nv + qrow0 + r) * Dv + h * Dhv + ch * 8;
        cp16(QS + r * 128 + ((ch ^ (r & 7)) << 4), src);
    }
    issueKV(0);
    if (n_kt > 1) issueKV(1);

    const float qn0 = g_qn[(size_t)bh * Nv + wr0 + (L >> 2)];
    const float qn1 = g_qn[(size_t)bh * Nv + wr0 + (L >> 2) + 8];
    const float cq0 = fmaf(C2, qn0, C0);
    const float cq1 = fmaf(C2, qn1, C0);

    float o[8][4];
#pragma unroll
    for (int j = 0; j < 8; j++)
#pragma unroll
        for (int e = 0; e < 4; e++) o[j][e] = 0.0f;
    float m0r = -1e30f, m1r = -1e30f, l0r = 0.0f, l1r = 0.0f;

#pragma unroll 1
    for (int kt = 0; kt < n_kt; kt++) {
        if (kt + 1 < n_kt) { CP_WAIT(1); } else { CP_WAIT(0); }
        __syncthreads();
        if (kt + 2 < n_kt) issueKV(kt + 2);
        const int k0 = kt * 64;
        const uint32_t sb = SB + AST0 + (uint32_t)(kt % 3) * ASTSZ;
        const float* kn_s = (const float*)(smem + AKN + (kt % 3) * 256);

        if (k0 <= wr0 + 15) {
            // ---- S = Q K^T (fp16 mma) ----
            float sc[8][4];
#pragma unroll
            for (int j = 0; j < 8; j++)
#pragma unroll
                for (int e = 0; e < 4; e++) sc[j][e] = 0.0f;
#pragma unroll
            for (int ks = 0; ks < 4; ks++) {
                uint32_t aq[4];
                {
                    int arow = w * 16 + (L & 15);
                    int ch = 2 * ks + (L >> 4);
                    LDSM4(aq[0], aq[1], aq[2], aq[3], QS + arow * 128 + ((ch ^ (arow & 7)) << 4));
                }
#pragma unroll
                for (int jn = 0; jn < 4; jn++) {
                    uint32_t bk[4];
                    int brow = jn * 16 + ((L >> 4) & 1) * 8 + (L & 7);
                    int ch = 2 * ks + ((L >> 3) & 1);
                    LDSM4(bk[0], bk[1], bk[2], bk[3], sb + brow * 128 + ((ch ^ (brow & 7)) << 4));
                    mma_f16(sc[2 * jn],     aq, bk[0], bk[1]);
                    mma_f16(sc[2 * jn + 1], aq, bk[2], bk[3]);
                }
            }

            // ---- distance -> scores ----
            const bool need_mask = (k0 + 63 > wr0);
            float vm0 = -1e30f, vm1 = -1e30f;
            if (!need_mask) {
                float damin = 1e30f;
#pragma unroll
                for (int j = 0; j < 8; j++) {
                    float2 kn2 = *(const float2*)(kn_s + 8 * j + 2 * (L & 3));
                    float d0 = fmaf(-2.0f, sc[j][0], qn0 + kn2.x);
                    float d1 = fmaf(-2.0f, sc[j][1], qn0 + kn2.y);
                    float d2 = fmaf(-2.0f, sc[j][2], qn1 + kn2.x);
                    float d3 = fmaf(-2.0f, sc[j][3], qn1 + kn2.y);
                    damin = fminf(damin, fminf(fminf(d0, d1), fminf(d2, d3)));
                    float s0 = fmaf(C1, f_lg2(d0), fmaf(C2, kn2.x, cq0));
                    float s1 = fmaf(C1, f_lg2(d1), fmaf(C2, kn2.y, cq0));
                    float s2v = fmaf(C1, f_lg2(d2), fmaf(C2, kn2.x, cq1));
                    float s3 = fmaf(C1, f_lg2(d3), fmaf(C2, kn2.y, cq1));
                    sc[j][0] = s0; sc[j][1] = s1; sc[j][2] = s2v; sc[j][3] = s3;
                    vm0 = fmaxf(vm0, fmaxf(s0, s1));
                    vm1 = fmaxf(vm1, fmaxf(s2v, s3));
                }
                if (damin < 4.0f) {
                    vm0 = -1e30f; vm1 = -1e30f;
                    const float invC1 = 1.0f / C1;
#pragma unroll
                    for (int j = 0; j < 8; j++) {
                        float2 kn2 = *(const float2*)(kn_s + 8 * j + 2 * (L & 3));
#pragma unroll
                        for (int e = 0; e < 4; e++) {
                            float qn = (e < 2) ? qn0 : qn1;
                            float cq = (e < 2) ? cq0 : cq1;
                            float kn = (e & 1) ? kn2.y : kn2.x;
                            float base = fmaf(C2, kn, cq);
                            float da = f_ex2((sc[j][e] - base) * invC1);
                            float s2 = sc[j][e];
                            if (!(da > 4.0f)) {
                                float ns = qn + kn;
                                float ed = f_sqrt(fmaxf(da, 0.0f) + 1e-8f);
                                float dist;
                                if (ed < 0.1f) {
                                    float cn = cc * ns;
                                    dist = ed * (1.0f + 0.5f * cn + 0.125f * cn * cn);
                                } else if (ed > 2.0f) {
                                    dist = 0.693f + 0.6931472f * f_lg2(ed + 1e-8f) + cc * ns * 0.25f;
                                } else {
                                    dist = ed * f_sqrt(1.0f + cc * ns);
                                }
                                s2 = -bL2E * dist;
                            }
                            sc[j][e] = s2;
                            if (e < 2) vm0 = fmaxf(vm0, s2); else vm1 = fmaxf(vm1, s2);
                        }
                    }
                }
            } else {
                const int rg0 = wr0 + (L >> 2), rg1 = rg0 + 8;
#pragma unroll
                for (int j = 0; j < 8; j++) {
                    float2 kn2 = *(const float2*)(kn_s + 8 * j + 2 * (L & 3));
                    const int cg = k0 + 8 * j + 2 * (L & 3);
#pragma unroll
                    for (int e = 0; e < 4; e++) {
                        float qn = (e < 2) ? qn0 : qn1;
                        float kn = (e & 1) ? kn2.y : kn2.x;
                        float ns = qn + kn;
                        float da = fmaxf(fmaf(-2.0f, sc[j][e], ns), 0.0f) + 1e-8f;
                        float s2;
                        if (da > 4.0f) {
                            s2 = fmaf(C1, f_lg2(da), fmaf(C2, ns, C0));
                        } else {
                            float ed = f_sqrt(da);
                            float dist;
                            if (ed < 0.1f) {
                                float cn = cc * ns;
                                dist = ed * (1.0f + 0.5f * cn + 0.125f * cn * cn);
                            } else if (ed > 2.0f) {
                                dist = 0.693f + 0.6931472f * f_lg2(ed + 1e-8f) + cc * ns * 0.25f;
                            } else {
                                dist = ed * f_sqrt(1.0f + cc * ns);
                            }
                            s2 = -bL2E * dist;
                        }
                        int rowg = (e < 2) ? rg0 : rg1;
                        if (cg + (e & 1) > rowg) s2 = -1e30f;
                        sc[j][e] = s2;
                        if (e < 2) vm0 = fmaxf(vm0, s2); else vm1 = fmaxf(vm1, s2);
                    }
                }
            }
            vm0 = fmaxf(vm0, __shfl_xor_sync(0xffffffffu, vm0, 1));
            vm0 = fmaxf(vm0, __shfl_xor_sync(0xffffffffu, vm0, 2));
            vm1 = fmaxf(vm1, __shfl_xor_sync(0xffffffffu, vm1, 1));
            vm1 = fmaxf(vm1, __shfl_xor_sync(0xffffffffu, vm1, 2));

            float mn0 = fmaxf(m0r, vm0), mn1 = fmaxf(m1r, vm1);
            float corr0 = f_ex2(m0r - mn0), corr1 = f_ex2(m1r - mn1);
            m0r = mn0; m1r = mn1;

            float rs0 = 0.0f, rs1 = 0.0f;
#pragma unroll
            for (int j = 0; j < 8; j++) {
                float p0 = f_ex2(sc[j][0] - mn0);
                float p1 = f_ex2(sc[j][1] - mn0);
                float p2 = f_ex2(sc[j][2] - mn1);
                float p3 = f_ex2(sc[j][3] - mn1);
                sc[j][0] = p0; sc[j][1] = p1; sc[j][2] = p2; sc[j][3] = p3;
                rs0 += p0 + p1; rs1 += p2 + p3;
            }
            rs0 += __shfl_xor_sync(0xffffffffu, rs0, 1);
            rs0 += __shfl_xor_sync(0xffffffffu, rs0, 2);
            rs1 += __shfl_xor_sync(0xffffffffu, rs1, 1);
            rs1 += __shfl_xor_sync(0xffffffffu, rs1, 2);
            l0r = l0r * corr0 + rs0;
            l1r = l1r * corr1 + rs1;
#pragma unroll
            for (int j = 0; j < 8; j++) {
                o[j][0] *= corr0; o[j][1] *= corr0;
                o[j][2] *= corr1; o[j][3] *= corr1;
            }

            // ---- PV: o += Ph*Vh ----
#pragma unroll
            for (int ks = 0; ks < 4; ks++) {
                const int j0 = 2 * ks, j1 = 2 * ks + 1;
                uint32_t aph[4];
                aph[0] = pack_h2(sc[j0][0], sc[j0][1]);
                aph[1] = pack_h2(sc[j0][2], sc[j0][3]);
                aph[2] = pack_h2(sc[j1][0], sc[j1][1]);
                aph[3] = pack_h2(sc[j1][2], sc[j1][3]);
                const int krow = 16 * ks + (L & 15);
#pragma unroll
                for (int jd = 0; jd < 4; jd++) {
                    int ch = 2 * jd + (L >> 4);
                    uint32_t voff = (uint32_t)(krow * 128 + ((ch ^ (krow & 7)) << 4));
                    uint32_t vhf[4];
                    LDSM4T(vhf[0], vhf[1], vhf[2], vhf[3], sb + 8192 + voff);
                    mma_f16(o[2 * jd],     aph, vhf[0], vhf[1]);
                    mma_f16(o[2 * jd + 1], aph, vhf[2], vhf[3]);
                }
            }
        }
    }

    // ---- epilogue: O normalized, single fp16 ----
    const float inv0 = 1.0f / l0r, inv1 = 1.0f / l1r;
    const size_t base0 = (size_t)(b * Nv + wr0 + (L >> 2)) * Dv + h * Dhv + 2 * (L & 3);
    const size_t base1 = base0 + 8 * (size_t)Dv;
#pragma unroll
    for (int j = 0; j < 8; j++) {
        *(uint32_t*)(g_Of + base0 + 8 * j) = pack_h2(o[j][0] * inv0, o[j][1] * inv0);
        *(uint32_t*)(g_Of + base1 + 8 * j) = pack_h2(o[j][2] * inv1, o[j][3] * inv1);
    }
}

// ---------------------------------------------------------------------------
// Launch
// ---------------------------------------------------------------------------
extern "C" void kernel_launch(void* const* d_in, const int* in_sizes, int n_in,
                              void* d_out, int out_size) {
    const float* x  = (const float*)d_in[0];
    const float* Wq = (const float*)d_in[1];
    const float* Wk = (const float*)d_in[2];
    const float* Wv = (const float*)d_in[3];
    const float* Wo = (const float*)d_in[4];
    const float* lc = (const float*)d_in[5];
    const float* lb = (const float*)d_in[6];
    float* out = (float*)d_out;

    cudaFuncSetAttribute(proj_qkv_cp, cudaFuncAttributeMaxDynamicSharedMemorySize, GEMM_SMEM);
    cudaFuncSetAttribute(out_proj_cp, cudaFuncAttributeMaxDynamicSharedMemorySize, GEMM_SMEM);
    cudaFuncSetAttribute(attn_cp,     cudaFuncAttributeMaxDynamicSharedMemorySize, ASMEM);

    prep_split<<<dim3(4096, 1, 5), 256>>>(x, Wq, Wk, Wv, Wo);
    proj_qkv_cp<<<dim3(8, 32, 3), 256, GEMM_SMEM>>>();
    attn_cp<<<dim3(Nv / 128, Bv * Hv), 256, ASMEM>>>(lc, lb);
    out_proj_cp<<<dim3(8, 32), 256, GEMM_SMEM>>>(out);
}

// round 16
// speedup vs baseline: 1.0806x; 1.0170x over previous
#include <cuda_runtime.h>
#include <cuda_fp16.h>
#include <math.h>
#include <stdint.h>

#define Bv 2
#define Nv 2048
#define Dv 1024
#define Hv 16
#define Dhv 64
#define Mrows (Bv * Nv)   // 4096

// ---------------------------------------------------------------------------
// Scratch (fp16 split formats)
// ---------------------------------------------------------------------------
__device__ __half g_x16[Mrows * Dv];
__device__ __half g_Wqh16[Dv * Dv], g_Wql16[Dv * Dv];
__device__ __half g_Wkh16[Dv * Dv], g_Wkl16[Dv * Dv];
__device__ __half g_Wvh16[Dv * Dv], g_Wvl16[Dv * Dv];
__device__ __half g_Woh16[Dv * Dv], g_Wol16[Dv * Dv];
__device__ __half g_Qh[Mrows * Dv], g_Kh[Mrows * Dv];
__device__ __half g_Vh[Mrows * Dv];
__device__ __half g_Of[Mrows * Dv];
__device__ float  g_qn[Bv * Hv * Nv], g_kn[Bv * Hv * Nv];

// ---------------------------------------------------------------------------
// Helpers (plain-sm_100-safe PTX only)
// ---------------------------------------------------------------------------
__device__ __forceinline__ uint32_t smem_u32(const void* p) {
    uint32_t a;
    asm("{ .reg .u64 t; cvta.to.shared.u64 t, %1; cvt.u32.u64 %0, t; }" : "=r"(a) : "l"(p));
    return a;
}
__device__ __forceinline__ void cp16(uint32_t dst, const void* src) {
    asm volatile("cp.async.cg.shared.global [%0], [%1], 16;" :: "r"(dst), "l"(src) : "memory");
}
#define CP_COMMIT() asm volatile("cp.async.commit_group;" ::: "memory")
#define CP_WAIT(n)  asm volatile("cp.async.wait_group %0;" :: "n"(n) : "memory")

#define LDSM4(r0, r1, r2, r3, addr) \
    asm volatile("ldmatrix.sync.aligned.m8n8.x4.shared.b16 {%0,%1,%2,%3}, [%4];" \
        : "=r"(r0), "=r"(r1), "=r"(r2), "=r"(r3) : "r"(addr))
#define LDSM4T(r0, r1, r2, r3, addr) \
    asm volatile("ldmatrix.sync.aligned.m8n8.x4.trans.shared.b16 {%0,%1,%2,%3}, [%4];" \
        : "=r"(r0), "=r"(r1), "=r"(r2), "=r"(r3) : "r"(addr))

__device__ __forceinline__ void mma_f16(float* d, const uint32_t* a, uint32_t b0, uint32_t b1) {
    asm volatile("mma.sync.aligned.m16n8k16.row.col.f32.f16.f16.f32 "
        "{%0,%1,%2,%3}, {%4,%5,%6,%7}, {%8,%9}, {%0,%1,%2,%3};"
        : "+f"(d[0]), "+f"(d[1]), "+f"(d[2]), "+f"(d[3])
        : "r"(a[0]), "r"(a[1]), "r"(a[2]), "r"(a[3]), "r"(b0), "r"(b1));
}

__device__ __forceinline__ uint32_t pack_h2(float lo, float hi) {
    __half2 h = __floats2half2_rn(lo, hi);
    return *(uint32_t*)&h;
}
__device__ __forceinline__ void hsplit2(float a, float b, uint32_t& h, uint32_t& l) {
    h = pack_h2(a, b);
    float2 f = __half22float2(*(__half2*)&h);
    l = pack_h2(a - f.x, b - f.y);
}

__device__ __forceinline__ float f_lg2(float x) { float r; asm("lg2.approx.f32 %0, %1;" : "=f"(r) : "f"(x)); return r; }
__device__ __forceinline__ float f_ex2(float x) { float r; asm("ex2.approx.f32 %0, %1;" : "=f"(r) : "f"(x)); return r; }
__device__ __forceinline__ float f_sqrt(float x){ float r; asm("sqrt.approx.f32 %0, %1;" : "=f"(r) : "f"(x)); return r; }

// ---------------------------------------------------------------------------
// Prep: x -> fp16; each W -> fp16 hi/lo. Flat 1D grid, no empty blocks:
// blocks [0,4096) handle x (16 f32/thread span), [4096,8192) handle the 4 Ws
// (1024 blocks each).
// ---------------------------------------------------------------------------
__global__ void prep_split(const float* __restrict__ x, const float* __restrict__ Wq,
                           const float* __restrict__ Wk, const float* __restrict__ Wv,
                           const float* __restrict__ Wo) {
    int blk = blockIdx.x;
    if (blk < 4096) {
        int i = (blk * 256 + threadIdx.x) * 4;
        float4 v = *(const float4*)(x + i);
        uint32_t h01 = pack_h2(v.x, v.y), h23 = pack_h2(v.z, v.w);
        *(uint32_t*)(g_x16 + i) = h01; *(uint32_t*)(g_x16 + i + 2) = h23;
        return;
    }
    blk -= 4096;
    const int which = blk >> 10;           // 0..3
    const int wblk  = blk & 1023;
    const float* src; __half *hi, *lo;
    switch (which) {
        case 0:  src = Wq; hi = g_Wqh16; lo = g_Wql16; break;
        case 1:  src = Wk; hi = g_Wkh16; lo = g_Wkl16; break;
        case 2:  src = Wv; hi = g_Wvh16; lo = g_Wvl16; break;
        default: src = Wo; hi = g_Woh16; lo = g_Wol16; break;
    }
    int i = (wblk * 256 + threadIdx.x) * 4;
    float4 v = *(const float4*)(src + i);
    uint32_t h01, l01, h23, l23;
    hsplit2(v.x, v.y, h01, l01);
    hsplit2(v.z, v.w, h23, l23);
    *(uint32_t*)(hi + i) = h01; *(uint32_t*)(hi + i + 2) = h23;
    *(uint32_t*)(lo + i) = l01; *(uint32_t*)(lo + i + 2) = l23;
}

// ---------------------------------------------------------------------------
// 2xFP16 GEMM (R11-proven, unchanged): D = Ah @ (Wh + Wl)^T.
// Stage = Ah | Wh | Wl (8KB each, SW64); 3-stage cp.async ring, 2 CTAs/SM.
// ---------------------------------------------------------------------------
#define GSTAGE    24576
#define GEMM_SMEM (3 * GSTAGE)

__device__ __forceinline__ void gemm_cp_body(
    const __half* __restrict__ Ah,
    const __half* __restrict__ Wh, const __half* __restrict__ Wl,
    int mode, __half* outH, float* fout, float* nrm_out)
{
    extern __shared__ char smem[];
    const uint32_t SB = smem_u32(smem);
    const int t = threadIdx.x, L = t & 31, wid = t >> 5;
    const int wm = wid >> 2, wn = wid & 3;
    const int m0 = blockIdx.y * 128, n0 = blockIdx.x * 128;

    auto issue = [&](int kc) {
        const int k0 = kc * 32;
        const uint32_t sbase = SB + (uint32_t)(kc % 3) * GSTAGE;
#pragma unroll
        for (int u = 0; u < 6; u++) {
            int idx = t + 256 * u;
            int tile = idx >> 9, r = (idx >> 2) & 127, ch = idx & 3;
            const __half* base = (tile == 0) ? Ah : (tile == 1) ? Wh : Wl;
            int grow = ((tile == 0) ? m0 : n0) + r;
            const void* src = base + (size_t)grow * 1024 + k0 + ch * 8;
            cp16(sbase + tile * 8192 + r * 64 + (((ch ^ ((r >> 1) & 3)) << 4)), src);
        }
        CP_COMMIT();
    };

    issue(0);
    issue(1);

    const int arow = wm * 64 + (L & 15);
    const int brow = wn * 32 + ((L >> 4) & 1) * 8 + (L & 7);
    const uint32_t aRowOff = (uint32_t)(arow * 64);
    const uint32_t bhOff = (uint32_t)(8192 + brow * 64);
    const uint32_t blOff = (uint32_t)(16384 + brow * 64);
    const uint32_t aXr = (uint32_t)((arow >> 1) & 3);
    const uint32_t bXr = (uint32_t)((brow >> 1) & 3);

    float acc[4][4][4];
#pragma unroll
    for (int i = 0; i < 4; i++)
#pragma unroll
        for (int j = 0; j < 4; j++)
#pragma unroll
            for (int r = 0; r < 4; r++) acc[i][j][r] = 0.0f;

#pragma unroll 1
    for (int kc = 0; kc < 32; kc++) {
        if (kc < 31) { CP_WAIT(1); } else { CP_WAIT(0); }
        __syncthreads();
        if (kc + 2 < 32) issue(kc + 2);
        const uint32_t sb = SB + (uint32_t)(kc % 3) * GSTAGE;
#pragma unroll
        for (int js = 0; js < 2; js++) {
            const uint32_t achunk = (uint32_t)((((2 * js + (L >> 4)) ^ aXr) << 4));
            const uint32_t bchunk = (uint32_t)((((2 * js + ((L >> 3) & 1)) ^ bXr) << 4));
            uint32_t ah[4][4];
#pragma unroll
            for (int i = 0; i < 4; i++)
                LDSM4(ah[i][0], ah[i][1], ah[i][2], ah[i][3], sb + aRowOff + i * 1024 + achunk);
#pragma unroll
            for (int jp = 0; jp < 2; jp++) {
                uint32_t bh[4], bl[4];
                LDSM4(bh[0], bh[1], bh[2], bh[3], sb + bhOff + jp * 1024 + bchunk);
                LDSM4(bl[0], bl[1], bl[2], bl[3], sb + blOff + jp * 1024 + bchunk);
#pragma unroll
                for (int i = 0; i < 4; i++) {
                    mma_f16(acc[i][jp * 2],     ah[i], bh[0], bh[1]);
                    mma_f16(acc[i][jp * 2 + 1], ah[i], bh[2], bh[3]);
                }
#pragma unroll
                for (int i = 0; i < 4; i++) {
                    mma_f16(acc[i][jp * 2],     ah[i], bl[0], bl[1]);
                    mma_f16(acc[i][jp * 2 + 1], ah[i], bl[2], bl[3]);
                }
            }
        }
    }

    const int rb = m0 + wm * 64 + (L >> 2);
    const int cb = n0 + wn * 32 + (L & 3) * 2;

    if (mode <= 1) {
        float p0s[4], p1s[4];
#pragma unroll
        for (int i = 0; i < 4; i++) {
            float s0 = 0.0f, s1 = 0.0f;
#pragma unroll
            for (int j = 0; j < 4; j++) {
                const int r = rb + i * 16, c = cb + j * 8;
                *(__half2*)(outH + (size_t)r * 1024 + c)       = __floats2half2_rn(acc[i][j][0], acc[i][j][1]);
                *(__half2*)(outH + (size_t)(r + 8) * 1024 + c) = __floats2half2_rn(acc[i][j][2], acc[i][j][3]);
                s0 = fmaf(acc[i][j][0], acc[i][j][0], fmaf(acc[i][j][1], acc[i][j][1], s0));
                s1 = fmaf(acc[i][j][2], acc[i][j][2], fmaf(acc[i][j][3], acc[i][j][3], s1));
            }
            s0 += __shfl_xor_sync(0xffffffffu, s0, 1);
            s0 += __shfl_xor_sync(0xffffffffu, s0, 2);
            s1 += __shfl_xor_sync(0xffffffffu, s1, 1);
            s1 += __shfl_xor_sync(0xffffffffu, s1, 2);
            p0s[i] = s0; p1s[i] = s1;
        }
        __syncthreads();
        float* part = (float*)smem;
        if ((L & 3) == 0) {
#pragma unroll
            for (int i = 0; i < 4; i++) {
                int r0 = wm * 64 + (L >> 2) + i * 16;
                part[r0 * 4 + wn] = p0s[i];
                part[(r0 + 8) * 4 + wn] = p1s[i];
            }
        }
        __syncthreads();
        {
            int row = t >> 1, ph = t & 1;
            float s = part[row * 4 + 2 * ph] + part[row * 4 + 2 * ph + 1];
            int grow = m0 + row, head = (n0 >> 6) + ph;
            int b = grow >> 11, n = grow & 2047;
            nrm_out[((b << 4) + head) * Nv + n] = s;
        }
    } else if (mode == 2) {
#pragma unroll
        for (int i = 0; i < 4; i++)
#pragma unroll
            for (int j = 0; j < 4; j++) {
                const int r = rb + i * 16, c = cb + j * 8;
                *(__half2*)(outH + (size_t)r * 1024 + c)       = __floats2half2_rn(acc[i][j][0], acc[i][j][1]);
                *(__half2*)(outH + (size_t)(r + 8) * 1024 + c) = __floats2half2_rn(acc[i][j][2], acc[i][j][3]);
            }
    } else {
#pragma unroll
        for (int i = 0; i < 4; i++)
#pragma unroll
            for (int j = 0; j < 4; j++) {
                const int r = rb + i * 16, cx = cb + j * 8;
                *(float2*)(fout + (size_t)r * 1024 + cx)       = make_float2(acc[i][j][0], acc[i][j][1]);
                *(float2*)(fout + (size_t)(r + 8) * 1024 + cx) = make_float2(acc[i][j][2], acc[i][j][3]);
            }
    }
}

__global__ __launch_bounds__(256, 2)
void proj_qkv_cp() {
    if (blockIdx.z == 0)
        gemm_cp_body(g_x16, g_Wqh16, g_Wql16, 0, g_Qh, nullptr, g_qn);
    else if (blockIdx.z == 1)
        gemm_cp_body(g_x16, g_Wkh16, g_Wkl16, 1, g_Kh, nullptr, g_kn);
    else
        gemm_cp_body(g_x16, g_Wvh16, g_Wvl16, 2, g_Vh, nullptr, nullptr);
}

__global__ __launch_bounds__(256, 2)
void out_proj_cp(float* __restrict__ out) {
    gemm_cp_body(g_Of, g_Woh16, g_Wol16, 3, nullptr, out, nullptr);
}

// ---------------------------------------------------------------------------
// Hyperbolic flash attention — R11-proven configuration (measured optimum):
// 64-wide tiles, 3-stage cp.async ring, single sync/tile, thin asymptotic
// score path with cold exact fallback, single-product PV, unconditional
// running-max correction.
// ---------------------------------------------------------------------------
#define AST0  16384
#define ASTSZ 16384
#define AKN   (AST0 + 3 * ASTSZ)          // 65536
#define ASMEM (AKN + 3 * 256)             // 66304

__global__ __launch_bounds__(256, 2)
void attn_cp(const float* __restrict__ lc_p, const float* __restrict__ lb_p) {
    extern __shared__ char smem[];
    const uint32_t SB = smem_u32(smem);
    const uint32_t QS = SB;

    const int t = threadIdx.x;
    const int L = t & 31;
    const int w = t >> 5;
    const int bh = blockIdx.y;
    const int b  = bh >> 4, h = bh & 15;
    const int qx = (int)gridDim.x - 1 - (int)blockIdx.x;
    const int qrow0 = qx * 128;
    const int wr0 = qrow0 + w * 16;

    const float cc = log1pf(expf(*lc_p));
    const float bb = log1pf(expf(*lb_p)) + 0.5f;
    const float bL2E = bb * 1.4426950408889634f;
    const float C0 = -bL2E * 0.693f;
    const float C1 = -bL2E * 0.34657359f;
    const float C2 = -bL2E * cc * 0.25f;

    const int n_kt = 2 * qx + 2;

    auto issueKV = [&](int kt) {
        const int k0 = kt * 64;
        const uint32_t sb = SB + AST0 + (uint32_t)(kt % 3) * ASTSZ;
#pragma unroll
        for (int u = 0; u < 4; u++) {
            int idx = t + 256 * u;
            int tile = idx >> 9, r = (idx >> 3) & 63, ch = idx & 7;
            const __half* base = (tile == 0) ? g_Kh : g_Vh;
            const void* src = base + (size_t)(b * Nv + k0 + r) * Dv + h * Dhv + ch * 8;
            cp16(sb + tile * 8192 + r * 128 + ((ch ^ (r & 7)) << 4), src);
        }
        if (t < 16)
            cp16(SB + AKN + (kt % 3) * 256 + t * 16, g_kn + (size_t)bh * Nv + k0 + t * 4);
        CP_COMMIT();
    };

#pragma unroll
    for (int u = 0; u < 4; u++) {
        int idx = t + 256 * u;
        int r = idx >> 3, ch = idx & 7;
        const void* src = g_Qh + (size_t)(b * Nv + qrow0 + r) * Dv + h * Dhv + ch * 8;
        cp16(QS + r * 128 + ((ch ^ (r & 7)) << 4), src);
    }
    issueKV(0);
    if (n_kt > 1) issueKV(1);

    const float qn0 = g_qn[(size_t)bh * Nv + wr0 + (L >> 2)];
    const float qn1 = g_qn[(size_t)bh * Nv + wr0 + (L >> 2) + 8];
    const float cq0 = fmaf(C2, qn0, C0);
    const float cq1 = fmaf(C2, qn1, C0);

    float o[8][4];
#pragma unroll
    for (int j = 0; j < 8; j++)
#pragma unroll
        for (int e = 0; e < 4; e++) o[j][e] = 0.0f;
    float m0r = -1e30f, m1r = -1e30f, l0r = 0.0f, l1r = 0.0f;

#pragma unroll 1
    for (int kt = 0; kt < n_kt; kt++) {
        if (kt + 1 < n_kt) { CP_WAIT(1); } else { CP_WAIT(0); }
        __syncthreads();
        if (kt + 2 < n_kt) issueKV(kt + 2);
        const int k0 = kt * 64;
        const uint32_t sb = SB + AST0 + (uint32_t)(kt % 3) * ASTSZ;
        const float* kn_s = (const float*)(smem + AKN + (kt % 3) * 256);

        if (k0 <= wr0 + 15) {
            // ---- S = Q K^T (fp16 mma) ----
            float sc[8][4];
#pragma unroll
            for (int j = 0; j < 8; j++)
#pragma unroll
                for (int e = 0; e < 4; e++) sc[j][e] = 0.0f;
#pragma unroll
            for (int ks = 0; ks < 4; ks++) {
                uint32_t aq[4];
                {
                    int arow = w * 16 + (L & 15);
                    int ch = 2 * ks + (L >> 4);
                    LDSM4(aq[0], aq[1], aq[2], aq[3], QS + arow * 128 + ((ch ^ (arow & 7)) << 4));
                }
#pragma unroll
                for (int jn = 0; jn < 4; jn++) {
                    uint32_t bk[4];
                    int brow = jn * 16 + ((L >> 4) & 1) * 8 + (L & 7);
                    int ch = 2 * ks + ((L >> 3) & 1);
                    LDSM4(bk[0], bk[1], bk[2], bk[3], sb + brow * 128 + ((ch ^ (brow & 7)) << 4));
                    mma_f16(sc[2 * jn],     aq, bk[0], bk[1]);
                    mma_f16(sc[2 * jn + 1], aq, bk[2], bk[3]);
                }
            }

            // ---- distance -> scores ----
            const bool need_mask = (k0 + 63 > wr0);
            float vm0 = -1e30f, vm1 = -1e30f;
            if (!need_mask) {
                float damin = 1e30f;
#pragma unroll
                for (int j = 0; j < 8; j++) {
                    float2 kn2 = *(const float2*)(kn_s + 8 * j + 2 * (L & 3));
                    float d0 = fmaf(-2.0f, sc[j][0], qn0 + kn2.x);
                    float d1 = fmaf(-2.0f, sc[j][1], qn0 + kn2.y);
                    float d2 = fmaf(-2.0f, sc[j][2], qn1 + kn2.x);
                    float d3 = fmaf(-2.0f, sc[j][3], qn1 + kn2.y);
                    damin = fminf(damin, fminf(fminf(d0, d1), fminf(d2, d3)));
                    float s0 = fmaf(C1, f_lg2(d0), fmaf(C2, kn2.x, cq0));
                    float s1 = fmaf(C1, f_lg2(d1), fmaf(C2, kn2.y, cq0));
                    float s2v = fmaf(C1, f_lg2(d2), fmaf(C2, kn2.x, cq1));
                    float s3 = fmaf(C1, f_lg2(d3), fmaf(C2, kn2.y, cq1));
                    sc[j][0] = s0; sc[j][1] = s1; sc[j][2] = s2v; sc[j][3] = s3;
                    vm0 = fmaxf(vm0, fmaxf(s0, s1));
                    vm1 = fmaxf(vm1, fmaxf(s2v, s3));
                }
                if (damin < 4.0f) {
                    vm0 = -1e30f; vm1 = -1e30f;
                    const float invC1 = 1.0f / C1;
#pragma unroll
                    for (int j = 0; j < 8; j++) {
                        float2 kn2 = *(const float2*)(kn_s + 8 * j + 2 * (L & 3));
#pragma unroll
                        for (int e = 0; e < 4; e++) {
                            float qn = (e < 2) ? qn0 : qn1;
                            float cq = (e < 2) ? cq0 : cq1;
                            float kn = (e & 1) ? kn2.y : kn2.x;
                            float base = fmaf(C2, kn, cq);
                            float da = f_ex2((sc[j][e] - base) * invC1);
                            float s2 = sc[j][e];
                            if (!(da > 4.0f)) {
                                float ns = qn + kn;
                                float ed = f_sqrt(fmaxf(da, 0.0f) + 1e-8f);
                                float dist;
                                if (ed < 0.1f) {
                                    float cn = cc * ns;
                                    dist = ed * (1.0f + 0.5f * cn + 0.125f * cn * cn);
                                } else if (ed > 2.0f) {
                                    dist = 0.693f + 0.6931472f * f_lg2(ed + 1e-8f) + cc * ns * 0.25f;
                                } else {
                                    dist = ed * f_sqrt(1.0f + cc * ns);
                                }
                                s2 = -bL2E * dist;
                            }
                            sc[j][e] = s2;
                            if (e < 2) vm0 = fmaxf(vm0, s2); else vm1 = fmaxf(vm1, s2);
                        }
                    }
                }
            } else {
                const int rg0 = wr0 + (L >> 2), rg1 = rg0 + 8;
#pragma unroll
                for (int j = 0; j < 8; j++) {
                    float2 kn2 = *(const float2*)(kn_s + 8 * j + 2 * (L & 3));
                    const int cg = k0 + 8 * j + 2 * (L & 3);
#pragma unroll
                    for (int e = 0; e < 4; e++) {
                        float qn = (e < 2) ? qn0 : qn1;
                        float kn = (e & 1) ? kn2.y : kn2.x;
                        float ns = qn + kn;
                        float da = fmaxf(fmaf(-2.0f, sc[j][e], ns), 0.0f) + 1e-8f;
                        float s2;
                        if (da > 4.0f) {
                            s2 = fmaf(C1, f_lg2(da), fmaf(C2, ns, C0));
                        } else {
                            float ed = f_sqrt(da);
                            float dist;
                            if (ed < 0.1f) {
                                float cn = cc * ns;
                                dist = ed * (1.0f + 0.5f * cn + 0.125f * cn * cn);
                            } else if (ed > 2.0f) {
                                dist = 0.693f + 0.6931472f * f_lg2(ed + 1e-8f) + cc * ns * 0.25f;
                            } else {
                                dist = ed * f_sqrt(1.0f + cc * ns);
                            }
                            s2 = -bL2E * dist;
                        }
                        int rowg = (e < 2) ? rg0 : rg1;
                        if (cg + (e & 1) > rowg) s2 = -1e30f;
                        sc[j][e] = s2;
                        if (e < 2) vm0 = fmaxf(vm0, s2); else vm1 = fmaxf(vm1, s2);
                    }
                }
            }
            vm0 = fmaxf(vm0, __shfl_xor_sync(0xffffffffu, vm0, 1));
            vm0 = fmaxf(vm0, __shfl_xor_sync(0xffffffffu, vm0, 2));
            vm1 = fmaxf(vm1, __shfl_xor_sync(0xffffffffu, vm1, 1));
            vm1 = fmaxf(vm1, __shfl_xor_sync(0xffffffffu, vm1, 2));

            float mn0 = fmaxf(m0r, vm0), mn1 = fmaxf(m1r, vm1);
            float corr0 = f_ex2(m0r - mn0), corr1 = f_ex2(m1r - mn1);
            m0r = mn0; m1r = mn1;

            float rs0 = 0.0f, rs1 = 0.0f;
#pragma unroll
            for (int j = 0; j < 8; j++) {
                float p0 = f_ex2(sc[j][0] - mn0);
                float p1 = f_ex2(sc[j][1] - mn0);
                float p2 = f_ex2(sc[j][2] - mn1);
                float p3 = f_ex2(sc[j][3] - mn1);
                sc[j][0] = p0; sc[j][1] = p1; sc[j][2] = p2; sc[j][3] = p3;
                rs0 += p0 + p1; rs1 += p2 + p3;
            }
            rs0 += __shfl_xor_sync(0xffffffffu, rs0, 1);
            rs0 += __shfl_xor_sync(0xffffffffu, rs0, 2);
            rs1 += __shfl_xor_sync(0xffffffffu, rs1, 1);
            rs1 += __shfl_xor_sync(0xffffffffu, rs1, 2);
            l0r = l0r * corr0 + rs0;
            l1r = l1r * corr1 + rs1;
#pragma unroll
            for (int j = 0; j < 8; j++) {
                o[j][0] *= corr0; o[j][1] *= corr0;
                o[j][2] *= corr1; o[j][3] *= corr1;
            }

            // ---- PV: o += Ph*Vh ----
#pragma unroll
            for (int ks = 0; ks < 4; ks++) {
                const int j0 = 2 * ks, j1 = 2 * ks + 1;
                uint32_t aph[4];
                aph[0] = pack_h2(sc[j0][0], sc[j0][1]);
                aph[1] = pack_h2(sc[j0][2], sc[j0][3]);
                aph[2] = pack_h2(sc[j1][0], sc[j1][1]);
                aph[3] = pack_h2(sc[j1][2], sc[j1][3]);
                const int krow = 16 * ks + (L & 15);
#pragma unroll
                for (int jd = 0; jd < 4; jd++) {
                    int ch = 2 * jd + (L >> 4);
                    uint32_t voff = (uint32_t)(krow * 128 + ((ch ^ (krow & 7)) << 4));
                    uint32_t vhf[4];
                    LDSM4T(vhf[0], vhf[1], vhf[2], vhf[3], sb + 8192 + voff);
                    mma_f16(o[2 * jd],     aph, vhf[0], vhf[1]);
                    mma_f16(o[2 * jd + 1], aph, vhf[2], vhf[3]);
                }
            }
        }
    }

    // ---- epilogue: O normalized, single fp16 ----
    const float inv0 = 1.0f / l0r, inv1 = 1.0f / l1r;
    const size_t base0 = (size_t)(b * Nv + wr0 + (L >> 2)) * Dv + h * Dhv + 2 * (L & 3);
    const size_t base1 = base0 + 8 * (size_t)Dv;
#pragma unroll
    for (int j = 0; j < 8; j++) {
        *(uint32_t*)(g_Of + base0 + 8 * j) = pack_h2(o[j][0] * inv0, o[j][1] * inv0);
        *(uint32_t*)(g_Of + base1 + 8 * j) = pack_h2(o[j][2] * inv1, o[j][3] * inv1);
    }
}

// ---------------------------------------------------------------------------
// Launch
// ---------------------------------------------------------------------------
extern "C" void kernel_launch(void* const* d_in, const int* in_sizes, int n_in,
                              void* d_out, int out_size) {
    const float* x  = (const float*)d_in[0];
    const float* Wq = (const float*)d_in[1];
    const float* Wk = (const float*)d_in[2];
    const float* Wv = (const float*)d_in[3];
    const float* Wo = (const float*)d_in[4];
    const float* lc = (const float*)d_in[5];
    const float* lb = (const float*)d_in[6];
    float* out = (float*)d_out;

    cudaFuncSetAttribute(proj_qkv_cp, cudaFuncAttributeMaxDynamicSharedMemorySize, GEMM_SMEM);
    cudaFuncSetAttribute(out_proj_cp, cudaFuncAttributeMaxDynamicSharedMemorySize, GEMM_SMEM);
    cudaFuncSetAttribute(attn_cp,     cudaFuncAttributeMaxDynamicSharedMemorySize, ASMEM);

    prep_split<<<8192, 256>>>(x, Wq, Wk, Wv, Wo);            // flat grid, no empty blocks
    proj_qkv_cp<<<dim3(8, 32, 3), 256, GEMM_SMEM>>>();
    attn_cp<<<dim3(Nv / 128, Bv * Hv), 256, ASMEM>>>(lc, lb);
    out_proj_cp<<<dim3(8, 32), 256, GEMM_SMEM>>>(out);
}

// round 17
// speedup vs baseline: 1.2250x; 1.1336x over previous
#include <cuda_runtime.h>
#include <cuda_fp16.h>
#include <math.h>
#include <stdint.h>

#define Bv 2
#define Nv 2048
#define Dv 1024
#define Hv 16
#define Dhv 64
#define Mrows (Bv * Nv)   // 4096

// ---------------------------------------------------------------------------
// Scratch (fp16 split formats)
// ---------------------------------------------------------------------------
__device__ __half g_x16[Mrows * Dv];
__device__ __half g_Wqh16[Dv * Dv], g_Wql16[Dv * Dv];
__device__ __half g_Wkh16[Dv * Dv], g_Wkl16[Dv * Dv];
__device__ __half g_Wvh16[Dv * Dv], g_Wvl16[Dv * Dv];
__device__ __half g_Woh16[Dv * Dv], g_Wol16[Dv * Dv];
__device__ __half g_Qh[Mrows * Dv], g_Kh[Mrows * Dv];
__device__ __half g_Vh[Mrows * Dv];
__device__ __half g_Of[Mrows * Dv];
__device__ float  g_qn[Bv * Hv * Nv], g_kn[Bv * Hv * Nv];

// ---------------------------------------------------------------------------
// Helpers (plain-sm_100-safe PTX only)
// ---------------------------------------------------------------------------
__device__ __forceinline__ uint32_t smem_u32(const void* p) {
    uint32_t a;
    asm("{ .reg .u64 t; cvta.to.shared.u64 t, %1; cvt.u32.u64 %0, t; }" : "=r"(a) : "l"(p));
    return a;
}
__device__ __forceinline__ void cp16(uint32_t dst, const void* src) {
    asm volatile("cp.async.cg.shared.global [%0], [%1], 16;" :: "r"(dst), "l"(src) : "memory");
}
#define CP_COMMIT() asm volatile("cp.async.commit_group;" ::: "memory")
#define CP_WAIT(n)  asm volatile("cp.async.wait_group %0;" :: "n"(n) : "memory")

#define LDSM4(r0, r1, r2, r3, addr) \
    asm volatile("ldmatrix.sync.aligned.m8n8.x4.shared.b16 {%0,%1,%2,%3}, [%4];" \
        : "=r"(r0), "=r"(r1), "=r"(r2), "=r"(r3) : "r"(addr))
#define LDSM4T(r0, r1, r2, r3, addr) \
    asm volatile("ldmatrix.sync.aligned.m8n8.x4.trans.shared.b16 {%0,%1,%2,%3}, [%4];" \
        : "=r"(r0), "=r"(r1), "=r"(r2), "=r"(r3) : "r"(addr))

__device__ __forceinline__ void mma_f16(float* d, const uint32_t* a, uint32_t b0, uint32_t b1) {
    asm volatile("mma.sync.aligned.m16n8k16.row.col.f32.f16.f16.f32 "
        "{%0,%1,%2,%3}, {%4,%5,%6,%7}, {%8,%9}, {%0,%1,%2,%3};"
        : "+f"(d[0]), "+f"(d[1]), "+f"(d[2]), "+f"(d[3])
        : "r"(a[0]), "r"(a[1]), "r"(a[2]), "r"(a[3]), "r"(b0), "r"(b1));
}

__device__ __forceinline__ uint32_t pack_h2(float lo, float hi) {
    __half2 h = __floats2half2_rn(lo, hi);
    return *(uint32_t*)&h;
}
__device__ __forceinline__ void hsplit2(float a, float b, uint32_t& h, uint32_t& l) {
    h = pack_h2(a, b);
    float2 f = __half22float2(*(__half2*)&h);
    l = pack_h2(a - f.x, b - f.y);
}

__device__ __forceinline__ float f_lg2(float x) { float r; asm("lg2.approx.f32 %0, %1;" : "=f"(r) : "f"(x)); return r; }
__device__ __forceinline__ float f_ex2(float x) { float r; asm("ex2.approx.f32 %0, %1;" : "=f"(r) : "f"(x)); return r; }
__device__ __forceinline__ float f_sqrt(float x){ float r; asm("sqrt.approx.f32 %0, %1;" : "=f"(r) : "f"(x)); return r; }

// ---------------------------------------------------------------------------
// Prep: x -> fp16; each W -> fp16 hi/lo. Flat 1D grid, no empty blocks.
// ---------------------------------------------------------------------------
__global__ void prep_split(const float* __restrict__ x, const float* __restrict__ Wq,
                           const float* __restrict__ Wk, const float* __restrict__ Wv,
                           const float* __restrict__ Wo) {
    int blk = blockIdx.x;
    if (blk < 4096) {
        int i = (blk * 256 + threadIdx.x) * 4;
        float4 v = *(const float4*)(x + i);
        uint32_t h01 = pack_h2(v.x, v.y), h23 = pack_h2(v.z, v.w);
        *(uint32_t*)(g_x16 + i) = h01; *(uint32_t*)(g_x16 + i + 2) = h23;
        return;
    }
    blk -= 4096;
    const int which = blk >> 10;           // 0..3
    const int wblk  = blk & 1023;
    const float* src; __half *hi, *lo;
    switch (which) {
        case 0:  src = Wq; hi = g_Wqh16; lo = g_Wql16; break;
        case 1:  src = Wk; hi = g_Wkh16; lo = g_Wkl16; break;
        case 2:  src = Wv; hi = g_Wvh16; lo = g_Wvl16; break;
        default: src = Wo; hi = g_Woh16; lo = g_Wol16; break;
    }
    int i = (wblk * 256 + threadIdx.x) * 4;
    float4 v = *(const float4*)(src + i);
    uint32_t h01, l01, h23, l23;
    hsplit2(v.x, v.y, h01, l01);
    hsplit2(v.z, v.w, h23, l23);
    *(uint32_t*)(hi + i) = h01; *(uint32_t*)(hi + i + 2) = h23;
    *(uint32_t*)(lo + i) = l01; *(uint32_t*)(lo + i + 2) = l23;
}

// ---------------------------------------------------------------------------
// 2xFP16 GEMM (R11-proven, unchanged): D = Ah @ (Wh + Wl)^T.
// ---------------------------------------------------------------------------
#define GSTAGE    24576
#define GEMM_SMEM (3 * GSTAGE)

__device__ __forceinline__ void gemm_cp_body(
    const __half* __restrict__ Ah,
    const __half* __restrict__ Wh, const __half* __restrict__ Wl,
    int mode, __half* outH, float* fout, float* nrm_out)
{
    extern __shared__ char smem[];
    const uint32_t SB = smem_u32(smem);
    const int t = threadIdx.x, L = t & 31, wid = t >> 5;
    const int wm = wid >> 2, wn = wid & 3;
    const int m0 = blockIdx.y * 128, n0 = blockIdx.x * 128;

    auto issue = [&](int kc) {
        const int k0 = kc * 32;
        const uint32_t sbase = SB + (uint32_t)(kc % 3) * GSTAGE;
#pragma unroll
        for (int u = 0; u < 6; u++) {
            int idx = t + 256 * u;
            int tile = idx >> 9, r = (idx >> 2) & 127, ch = idx & 3;
            const __half* base = (tile == 0) ? Ah : (tile == 1) ? Wh : Wl;
            int grow = ((tile == 0) ? m0 : n0) + r;
            const void* src = base + (size_t)grow * 1024 + k0 + ch * 8;
            cp16(sbase + tile * 8192 + r * 64 + (((ch ^ ((r >> 1) & 3)) << 4)), src);
        }
        CP_COMMIT();
    };

    issue(0);
    issue(1);

    const int arow = wm * 64 + (L & 15);
    const int brow = wn * 32 + ((L >> 4) & 1) * 8 + (L & 7);
    const uint32_t aRowOff = (uint32_t)(arow * 64);
    const uint32_t bhOff = (uint32_t)(8192 + brow * 64);
    const uint32_t blOff = (uint32_t)(16384 + brow * 64);
    const uint32_t aXr = (uint32_t)((arow >> 1) & 3);
    const uint32_t bXr = (uint32_t)((brow >> 1) & 3);

    float acc[4][4][4];
#pragma unroll
    for (int i = 0; i < 4; i++)
#pragma unroll
        for (int j = 0; j < 4; j++)
#pragma unroll
            for (int r = 0; r < 4; r++) acc[i][j][r] = 0.0f;

#pragma unroll 1
    for (int kc = 0; kc < 32; kc++) {
        if (kc < 31) { CP_WAIT(1); } else { CP_WAIT(0); }
        __syncthreads();
        if (kc + 2 < 32) issue(kc + 2);
        const uint32_t sb = SB + (uint32_t)(kc % 3) * GSTAGE;
#pragma unroll
        for (int js = 0; js < 2; js++) {
            const uint32_t achunk = (uint32_t)((((2 * js + (L >> 4)) ^ aXr) << 4));
            const uint32_t bchunk = (uint32_t)((((2 * js + ((L >> 3) & 1)) ^ bXr) << 4));
            uint32_t ah[4][4];
#pragma unroll
            for (int i = 0; i < 4; i++)
                LDSM4(ah[i][0], ah[i][1], ah[i][2], ah[i][3], sb + aRowOff + i * 1024 + achunk);
#pragma unroll
            for (int jp = 0; jp < 2; jp++) {
                uint32_t bh[4], bl[4];
                LDSM4(bh[0], bh[1], bh[2], bh[3], sb + bhOff + jp * 1024 + bchunk);
                LDSM4(bl[0], bl[1], bl[2], bl[3], sb + blOff + jp * 1024 + bchunk);
#pragma unroll
                for (int i = 0; i < 4; i++) {
                    mma_f16(acc[i][jp * 2],     ah[i], bh[0], bh[1]);
                    mma_f16(acc[i][jp * 2 + 1], ah[i], bh[2], bh[3]);
                }
#pragma unroll
                for (int i = 0; i < 4; i++) {
                    mma_f16(acc[i][jp * 2],     ah[i], bl[0], bl[1]);
                    mma_f16(acc[i][jp * 2 + 1], ah[i], bl[2], bl[3]);
                }
            }
        }
    }

    const int rb = m0 + wm * 64 + (L >> 2);
    const int cb = n0 + wn * 32 + (L & 3) * 2;

    if (mode <= 1) {
        float p0s[4], p1s[4];
#pragma unroll
        for (int i = 0; i < 4; i++) {
            float s0 = 0.0f, s1 = 0.0f;
#pragma unroll
            for (int j = 0; j < 4; j++) {
                const int r = rb + i * 16, c = cb + j * 8;
                *(__half2*)(outH + (size_t)r * 1024 + c)       = __floats2half2_rn(acc[i][j][0], acc[i][j][1]);
                *(__half2*)(outH + (size_t)(r + 8) * 1024 + c) = __floats2half2_rn(acc[i][j][2], acc[i][j][3]);
                s0 = fmaf(acc[i][j][0], acc[i][j][0], fmaf(acc[i][j][1], acc[i][j][1], s0));
                s1 = fmaf(acc[i][j][2], acc[i][j][2], fmaf(acc[i][j][3], acc[i][j][3], s1));
            }
            s0 += __shfl_xor_sync(0xffffffffu, s0, 1);
            s0 += __shfl_xor_sync(0xffffffffu, s0, 2);
            s1 += __shfl_xor_sync(0xffffffffu, s1, 1);
            s1 += __shfl_xor_sync(0xffffffffu, s1, 2);
            p0s[i] = s0; p1s[i] = s1;
        }
        __syncthreads();
        float* part = (float*)smem;
        if ((L & 3) == 0) {
#pragma unroll
            for (int i = 0; i < 4; i++) {
                int r0 = wm * 64 + (L >> 2) + i * 16;
                part[r0 * 4 + wn] = p0s[i];
                part[(r0 + 8) * 4 + wn] = p1s[i];
            }
        }
        __syncthreads();
        {
            int row = t >> 1, ph = t & 1;
            float s = part[row * 4 + 2 * ph] + part[row * 4 + 2 * ph + 1];
            int grow = m0 + row, head = (n0 >> 6) + ph;
            int b = grow >> 11, n = grow & 2047;
            nrm_out[((b << 4) + head) * Nv + n] = s;
        }
    } else if (mode == 2) {
#pragma unroll
        for (int i = 0; i < 4; i++)
#pragma unroll
            for (int j = 0; j < 4; j++) {
                const int r = rb + i * 16, c = cb + j * 8;
                *(__half2*)(outH + (size_t)r * 1024 + c)       = __floats2half2_rn(acc[i][j][0], acc[i][j][1]);
                *(__half2*)(outH + (size_t)(r + 8) * 1024 + c) = __floats2half2_rn(acc[i][j][2], acc[i][j][3]);
            }
    } else {
#pragma unroll
        for (int i = 0; i < 4; i++)
#pragma unroll
            for (int j = 0; j < 4; j++) {
                const int r = rb + i * 16, cx = cb + j * 8;
                *(float2*)(fout + (size_t)r * 1024 + cx)       = make_float2(acc[i][j][0], acc[i][j][1]);
                *(float2*)(fout + (size_t)(r + 8) * 1024 + cx) = make_float2(acc[i][j][2], acc[i][j][3]);
            }
    }
}

__global__ __launch_bounds__(256, 2)
void proj_qkv_cp() {
    if (blockIdx.z == 0)
        gemm_cp_body(g_x16, g_Wqh16, g_Wql16, 0, g_Qh, nullptr, g_qn);
    else if (blockIdx.z == 1)
        gemm_cp_body(g_x16, g_Wkh16, g_Wkl16, 1, g_Kh, nullptr, g_kn);
    else
        gemm_cp_body(g_x16, g_Wvh16, g_Wvl16, 2, g_Vh, nullptr, nullptr);
}

__global__ __launch_bounds__(256, 2)
void out_proj_cp(float* __restrict__ out) {
    gemm_cp_body(g_Of, g_Woh16, g_Wol16, 3, nullptr, out, nullptr);
}

// ---------------------------------------------------------------------------
// Hyperbolic flash attention — R11 configuration with LPT dispatch order:
// grid (bh=32, qy=16), x fastest => all 32 longest CTAs (qx=15) dispatch
// first, then qx=14, ... Pure index relabeling; math identical.
// ---------------------------------------------------------------------------
#define AST0  16384
#define ASTSZ 16384
#define AKN   (AST0 + 3 * ASTSZ)          // 65536
#define ASMEM (AKN + 3 * 256)             // 66304

__global__ __launch_bounds__(256, 2)
void attn_cp(const float* __restrict__ lc_p, const float* __restrict__ lb_p) {
    extern __shared__ char smem[];
    const uint32_t SB = smem_u32(smem);
    const uint32_t QS = SB;

    const int t = threadIdx.x;
    const int L = t & 31;
    const int w = t >> 5;
    const int bh = blockIdx.x;                               // LPT: bh on x
    const int b  = bh >> 4, h = bh & 15;
    const int qx = (int)gridDim.y - 1 - (int)blockIdx.y;     // longest first
    const int qrow0 = qx * 128;
    const int wr0 = qrow0 + w * 16;

    const float cc = log1pf(expf(*lc_p));
    const float bb = log1pf(expf(*lb_p)) + 0.5f;
    const float bL2E = bb * 1.4426950408889634f;
    const float C0 = -bL2E * 0.693f;
    const float C1 = -bL2E * 0.34657359f;
    const float C2 = -bL2E * cc * 0.25f;

    const int n_kt = 2 * qx + 2;

    auto issueKV = [&](int kt) {
        const int k0 = kt * 64;
        const uint32_t sb = SB + AST0 + (uint32_t)(kt % 3) * ASTSZ;
#pragma unroll
        for (int u = 0; u < 4; u++) {
            int idx = t + 256 * u;
            int tile = idx >> 9, r = (idx >> 3) & 63, ch = idx & 7;
            const __half* base = (tile == 0) ? g_Kh : g_Vh;
            const void* src = base + (size_t)(b * Nv + k0 + r) * Dv + h * Dhv + ch * 8;
            cp16(sb + tile * 8192 + r * 128 + ((ch ^ (r & 7)) << 4), src);
        }
        if (t < 16)
            cp16(SB + AKN + (kt % 3) * 256 + t * 16, g_kn + (size_t)bh * Nv + k0 + t * 4);
        CP_COMMIT();
    };

#pragma unroll
    for (int u = 0; u < 4; u++) {
        int idx = t + 256 * u;
        int r = idx >> 3, ch = idx & 7;
        const void* src = g_Qh + (size_t)(b * Nv + qrow0 + r) * Dv + h * Dhv + ch * 8;
        cp16(QS + r * 128 + ((ch ^ (r & 7)) << 4), src);
    }
    issueKV(0);
    if (n_kt > 1) issueKV(1);

    const float qn0 = g_qn[(size_t)bh * Nv + wr0 + (L >> 2)];
    const float qn1 = g_qn[(size_t)bh * Nv + wr0 + (L >> 2) + 8];
    const float cq0 = fmaf(C2, qn0, C0);
    const float cq1 = fmaf(C2, qn1, C0);

    float o[8][4];
#pragma unroll
    for (int j = 0; j < 8; j++)
#pragma unroll
        for (int e = 0; e < 4; e++) o[j][e] = 0.0f;
    float m0r = -1e30f, m1r = -1e30f, l0r = 0.0f, l1r = 0.0f;

#pragma unroll 1
    for (int kt = 0; kt < n_kt; kt++) {
        if (kt + 1 < n_kt) { CP_WAIT(1); } else { CP_WAIT(0); }
        __syncthreads();
        if (kt + 2 < n_kt) issueKV(kt + 2);
        const int k0 = kt * 64;
        const uint32_t sb = SB + AST0 + (uint32_t)(kt % 3) * ASTSZ;
        const float* kn_s = (const float*)(smem + AKN + (kt % 3) * 256);

        if (k0 <= wr0 + 15) {
            // ---- S = Q K^T (fp16 mma) ----
            float sc[8][4];
#pragma unroll
            for (int j = 0; j < 8; j++)
#pragma unroll
                for (int e = 0; e < 4; e++) sc[j][e] = 0.0f;
#pragma unroll
            for (int ks = 0; ks < 4; ks++) {
                uint32_t aq[4];
                {
                    int arow = w * 16 + (L & 15);
                    int ch = 2 * ks + (L >> 4);
                    LDSM4(aq[0], aq[1], aq[2], aq[3], QS + arow * 128 + ((ch ^ (arow & 7)) << 4));
                }
#pragma unroll
                for (int jn = 0; jn < 4; jn++) {
                    uint32_t bk[4];
                    int brow = jn * 16 + ((L >> 4) & 1) * 8 + (L & 7);
                    int ch = 2 * ks + ((L >> 3) & 1);
                    LDSM4(bk[0], bk[1], bk[2], bk[3], sb + brow * 128 + ((ch ^ (brow & 7)) << 4));
                    mma_f16(sc[2 * jn],     aq, bk[0], bk[1]);
                    mma_f16(sc[2 * jn + 1], aq, bk[2], bk[3]);
                }
            }

            // ---- distance -> scores ----
            const bool need_mask = (k0 + 63 > wr0);
            float vm0 = -1e30f, vm1 = -1e30f;
            if (!need_mask) {
                float damin = 1e30f;
#pragma unroll
                for (int j = 0; j < 8; j++) {
                    float2 kn2 = *(const float2*)(kn_s + 8 * j + 2 * (L & 3));
                    float d0 = fmaf(-2.0f, sc[j][0], qn0 + kn2.x);
                    float d1 = fmaf(-2.0f, sc[j][1], qn0 + kn2.y);
                    float d2 = fmaf(-2.0f, sc[j][2], qn1 + kn2.x);
                    float d3 = fmaf(-2.0f, sc[j][3], qn1 + kn2.y);
                    damin = fminf(damin, fminf(fminf(d0, d1), fminf(d2, d3)));
                    float s0 = fmaf(C1, f_lg2(d0), fmaf(C2, kn2.x, cq0));
                    float s1 = fmaf(C1, f_lg2(d1), fmaf(C2, kn2.y, cq0));
                    float s2v = fmaf(C1, f_lg2(d2), fmaf(C2, kn2.x, cq1));
                    float s3 = fmaf(C1, f_lg2(d3), fmaf(C2, kn2.y, cq1));
                    sc[j][0] = s0; sc[j][1] = s1; sc[j][2] = s2v; sc[j][3] = s3;
                    vm0 = fmaxf(vm0, fmaxf(s0, s1));
                    vm1 = fmaxf(vm1, fmaxf(s2v, s3));
                }
                if (damin < 4.0f) {
                    vm0 = -1e30f; vm1 = -1e30f;
                    const float invC1 = 1.0f / C1;
#pragma unroll
                    for (int j = 0; j < 8; j++) {
                        float2 kn2 = *(const float2*)(kn_s + 8 * j + 2 * (L & 3));
#pragma unroll
                        for (int e = 0; e < 4; e++) {
                            float qn = (e < 2) ? qn0 : qn1;
                            float cq = (e < 2) ? cq0 : cq1;
                            float kn = (e & 1) ? kn2.y : kn2.x;
                            float base = fmaf(C2, kn, cq);
                            float da = f_ex2((sc[j][e] - base) * invC1);
                            float s2 = sc[j][e];
                            if (!(da > 4.0f)) {
                                float ns = qn + kn;
                                float ed = f_sqrt(fmaxf(da, 0.0f) + 1e-8f);
                                float dist;
                                if (ed < 0.1f) {
                                    float cn = cc * ns;
                                    dist = ed * (1.0f + 0.5f * cn + 0.125f * cn * cn);
                                } else if (ed > 2.0f) {
                                    dist = 0.693f + 0.6931472f * f_lg2(ed + 1e-8f) + cc * ns * 0.25f;
                                } else {
                                    dist = ed * f_sqrt(1.0f + cc * ns);
                                }
                                s2 = -bL2E * dist;
                            }
                            sc[j][e] = s2;
                            if (e < 2) vm0 = fmaxf(vm0, s2); else vm1 = fmaxf(vm1, s2);
                        }
                    }
                }
            } else {
                const int rg0 = wr0 + (L >> 2), rg1 = rg0 + 8;
#pragma unroll
                for (int j = 0; j < 8; j++) {
                    float2 kn2 = *(const float2*)(kn_s + 8 * j + 2 * (L & 3));
                    const int cg = k0 + 8 * j + 2 * (L & 3);
#pragma unroll
                    for (int e = 0; e < 4; e++) {
                        float qn = (e < 2) ? qn0 : qn1;
                        float kn = (e & 1) ? kn2.y : kn2.x;
                        float ns = qn + kn;
                        float da = fmaxf(fmaf(-2.0f, sc[j][e], ns), 0.0f) + 1e-8f;
                        float s2;
                        if (da > 4.0f) {
                            s2 = fmaf(C1, f_lg2(da), fmaf(C2, ns, C0));
                        } else {
                            float ed = f_sqrt(da);
                            float dist;
                            if (ed < 0.1f) {
                                float cn = cc * ns;
                                dist = ed * (1.0f + 0.5f * cn + 0.125f * cn * cn);
                            } else if (ed > 2.0f) {
                                dist = 0.693f + 0.6931472f * f_lg2(ed + 1e-8f) + cc * ns * 0.25f;
                            } else {
                                dist = ed * f_sqrt(1.0f + cc * ns);
                            }
                            s2 = -bL2E * dist;
                        }
                        int rowg = (e < 2) ? rg0 : rg1;
                        if (cg + (e & 1) > rowg) s2 = -1e30f;
                        sc[j][e] = s2;
                        if (e < 2) vm0 = fmaxf(vm0, s2); else vm1 = fmaxf(vm1, s2);
                    }
                }
            }
            vm0 = fmaxf(vm0, __shfl_xor_sync(0xffffffffu, vm0, 1));
            vm0 = fmaxf(vm0, __shfl_xor_sync(0xffffffffu, vm0, 2));
            vm1 = fmaxf(vm1, __shfl_xor_sync(0xffffffffu, vm1, 1));
            vm1 = fmaxf(vm1, __shfl_xor_sync(0xffffffffu, vm1, 2));

            float mn0 = fmaxf(m0r, vm0), mn1 = fmaxf(m1r, vm1);
            float corr0 = f_ex2(m0r - mn0), corr1 = f_ex2(m1r - mn1);
            m0r = mn0; m1r = mn1;

            float rs0 = 0.0f, rs1 = 0.0f;
#pragma unroll
            for (int j = 0; j < 8; j++) {
                float p0 = f_ex2(sc[j][0] - mn0);
                float p1 = f_ex2(sc[j][1] - mn0);
                float p2 = f_ex2(sc[j][2] - mn1);
                float p3 = f_ex2(sc[j][3] - mn1);
                sc[j][0] = p0; sc[j][1] = p1; sc[j][2] = p2; sc[j][3] = p3;
                rs0 += p0 + p1; rs1 += p2 + p3;
            }
            rs0 += __shfl_xor_sync(0xffffffffu, rs0, 1);
            rs0 += __shfl_xor_sync(0xffffffffu, rs0, 2);
            rs1 += __shfl_xor_sync(0xffffffffu, rs1, 1);
            rs1 += __shfl_xor_sync(0xffffffffu, rs1, 2);
            l0r = l0r * corr0 + rs0;
            l1r = l1r * corr1 + rs1;
#pragma unroll
            for (int j = 0; j < 8; j++) {
                o[j][0] *= corr0; o[j][1] *= corr0;
                o[j][2] *= corr1; o[j][3] *= corr1;
            }

            // ---- PV: o += Ph*Vh ----
#pragma unroll
            for (int ks = 0; ks < 4; ks++) {
                const int j0 = 2 * ks, j1 = 2 * ks + 1;
                uint32_t aph[4];
                aph[0] = pack_h2(sc[j0][0], sc[j0][1]);
                aph[1] = pack_h2(sc[j0][2], sc[j0][3]);
                aph[2] = pack_h2(sc[j1][0], sc[j1][1]);
                aph[3] = pack_h2(sc[j1][2], sc[j1][3]);
                const int krow = 16 * ks + (L & 15);
#pragma unroll
                for (int jd = 0; jd < 4; jd++) {
                    int ch = 2 * jd + (L >> 4);
                    uint32_t voff = (uint32_t)(krow * 128 + ((ch ^ (krow & 7)) << 4));
                    uint32_t vhf[4];
                    LDSM4T(vhf[0], vhf[1], vhf[2], vhf[3], sb + 8192 + voff);
                    mma_f16(o[2 * jd],     aph, vhf[0], vhf[1]);
                    mma_f16(o[2 * jd + 1], aph, vhf[2], vhf[3]);
                }
            }
        }
    }

    // ---- epilogue: O normalized, single fp16 ----
    const float inv0 = 1.0f / l0r, inv1 = 1.0f / l1r;
    const size_t base0 = (size_t)(b * Nv + wr0 + (L >> 2)) * Dv + h * Dhv + 2 * (L & 3);
    const size_t base1 = base0 + 8 * (size_t)Dv;
#pragma unroll
    for (int j = 0; j < 8; j++) {
        *(uint32_t*)(g_Of + base0 + 8 * j) = pack_h2(o[j][0] * inv0, o[j][1] * inv0);
        *(uint32_t*)(g_Of + base1 + 8 * j) = pack_h2(o[j][2] * inv1, o[j][3] * inv1);
    }
}

// ---------------------------------------------------------------------------
// Launch
// ---------------------------------------------------------------------------
extern "C" void kernel_launch(void* const* d_in, const int* in_sizes, int n_in,
                              void* d_out, int out_size) {
    const float* x  = (const float*)d_in[0];
    const float* Wq = (const float*)d_in[1];
    const float* Wk = (const float*)d_in[2];
    const float* Wv = (const float*)d_in[3];
    const float* Wo = (const float*)d_in[4];
    const float* lc = (const float*)d_in[5];
    const float* lb = (const float*)d_in[6];
    float* out = (float*)d_out;

    cudaFuncSetAttribute(proj_qkv_cp, cudaFuncAttributeMaxDynamicSharedMemorySize, GEMM_SMEM);
    cudaFuncSetAttribute(out_proj_cp, cudaFuncAttributeMaxDynamicSharedMemorySize, GEMM_SMEM);
    cudaFuncSetAttribute(attn_cp,     cudaFuncAttributeMaxDynamicSharedMemorySize, ASMEM);

    prep_split<<<8192, 256>>>(x, Wq, Wk, Wv, Wo);
    proj_qkv_cp<<<dim3(8, 32, 3), 256, GEMM_SMEM>>>();
    attn_cp<<<dim3(Bv * Hv, Nv / 128), 256, ASMEM>>>(lc, lb);   // LPT: bh on x, long qtiles first
    out_proj_cp<<<dim3(8, 32), 256, GEMM_SMEM>>>(out);
}